// round 1
// baseline (speedup 1.0000x reference)
#include <cuda_runtime.h>
#include <math.h>

// Problem constants (fixed by the dataset)
#define B_   4
#define T_   256
#define V_   1024
#define S_   64
#define DIM_ 1024
#define CV_  256

// ---------------------------------------------------------------------------
// Scratch (static device globals — no runtime allocation allowed)
// ---------------------------------------------------------------------------
__device__ float g_U [B_ * V_ * DIM_];   // vision @ Wu + bu      (16 MB)
__device__ float g_K [B_ * V_ * DIM_];   // U @ Wk                (16 MB)
__device__ float g_Vv[B_ * V_ * DIM_];   // U @ Wv                (16 MB)
__device__ int   g_sel  [B_ * T_ * S_];  // selected vision indices per (b,t)
__device__ float g_logit[B_ * T_ * S_];  // qk logits
__device__ float g_red  [B_ * 2];        // per-batch softmax max / sumexp

// ---------------------------------------------------------------------------
// 1) Extract the S=64 selected vision indices per (b,t) from the mask.
//    mask layout: (B, V, T); element is nonzero iff selected.
//    One warp per (b,t); ballot + prefix-popcount gives ascending order.
//    (Order is irrelevant downstream — attention sums over j — but ascending
//    matches the reference's index construction.)
// ---------------------------------------------------------------------------
__global__ void select_kernel(const int* __restrict__ mask) {
    int warp = (blockIdx.x * blockDim.x + threadIdx.x) >> 5;
    int lane = threadIdx.x & 31;
    if (warp >= B_ * T_) return;
    int b = warp / T_;
    int t = warp % T_;
    const int* m = mask + (size_t)b * V_ * T_ + t;   // stride T_ over v

    int count = 0;
    #pragma unroll 4
    for (int base = 0; base < V_; base += 32) {
        int v = base + lane;
        int val = m[(size_t)v * T_];                 // nonzero bits for int32 1 or float 1.0f
        unsigned bal = __ballot_sync(0xffffffffu, val != 0);
        if (val != 0) {
            int pos = count + __popc(bal & ((1u << lane) - 1u));
            if (pos < S_) g_sel[warp * S_ + pos] = v;
        }
        count += __popc(bal);
    }
}

// ---------------------------------------------------------------------------
// 2) FP32 SGEMM: C[M,N] = A[M,K] @ Bm[K,N] (+ bias[N] if bias != nullptr)
//    BM=BN=128, BK=8, 256 threads, 8x8 per-thread tile (split 4+4 at +64).
//    M,N multiples of 128; K multiple of 8 (all true here).
// ---------------------------------------------------------------------------
__global__ __launch_bounds__(256, 2)
void sgemm128(const float* __restrict__ A, const float* __restrict__ Bm,
              const float* __restrict__ bias, float* __restrict__ C,
              int M, int N, int K)
{
    __shared__ float As[8][128];
    __shared__ float Bs[8][128];

    int tid = threadIdx.x;
    int tx  = tid & 15;        // 0..15  -> N direction
    int ty  = tid >> 4;        // 0..15  -> M direction
    int m0  = blockIdx.y * 128;
    int n0  = blockIdx.x * 128;

    int arow = tid >> 1;              // 0..127
    int acol = (tid & 1) * 4;         // 0 or 4
    int brow = tid >> 5;              // 0..7
    int bcol = (tid & 31) * 4;        // 0..124

    const float* Aptr = A  + (size_t)(m0 + arow) * K + acol;
    const float* Bptr = Bm + (size_t)brow * N + n0 + bcol;

    float acc[8][8];
    #pragma unroll
    for (int i = 0; i < 8; i++)
        #pragma unroll
        for (int j = 0; j < 8; j++) acc[i][j] = 0.0f;

    for (int k0 = 0; k0 < K; k0 += 8) {
        float4 av = *(const float4*)Aptr;  Aptr += 8;
        float4 bv = *(const float4*)Bptr;  Bptr += (size_t)8 * N;

        As[acol + 0][arow] = av.x;
        As[acol + 1][arow] = av.y;
        As[acol + 2][arow] = av.z;
        As[acol + 3][arow] = av.w;
        *(float4*)&Bs[brow][bcol] = bv;
        __syncthreads();

        #pragma unroll
        for (int kk = 0; kk < 8; kk++) {
            float4 a0 = *(const float4*)&As[kk][ty * 4];
            float4 a1 = *(const float4*)&As[kk][64 + ty * 4];
            float4 b0 = *(const float4*)&Bs[kk][tx * 4];
            float4 b1 = *(const float4*)&Bs[kk][64 + tx * 4];
            float ar[8] = {a0.x, a0.y, a0.z, a0.w, a1.x, a1.y, a1.z, a1.w};
            float br[8] = {b0.x, b0.y, b0.z, b0.w, b1.x, b1.y, b1.z, b1.w};
            #pragma unroll
            for (int i = 0; i < 8; i++)
                #pragma unroll
                for (int j = 0; j < 8; j++)
                    acc[i][j] = fmaf(ar[i], br[j], acc[i][j]);
        }
        __syncthreads();
    }

    // Epilogue (+ optional bias)
    float4 bz0 = make_float4(0.f, 0.f, 0.f, 0.f);
    float4 bz1 = bz0;
    if (bias) {
        bz0 = *(const float4*)&bias[n0 + tx * 4];
        bz1 = *(const float4*)&bias[n0 + 64 + tx * 4];
    }
    #pragma unroll
    for (int i = 0; i < 8; i++) {
        int row = m0 + ((i < 4) ? (ty * 4 + i) : (64 + ty * 4 + (i - 4)));
        float* Crow = C + (size_t)row * N + n0;
        float4 o0 = make_float4(acc[i][0] + bz0.x, acc[i][1] + bz0.y,
                                acc[i][2] + bz0.z, acc[i][3] + bz0.w);
        float4 o1 = make_float4(acc[i][4] + bz1.x, acc[i][5] + bz1.y,
                                acc[i][6] + bz1.z, acc[i][7] + bz1.w);
        *(float4*)&Crow[tx * 4]      = o0;
        *(float4*)&Crow[64 + tx * 4] = o1;
    }
}

// ---------------------------------------------------------------------------
// 3) Logits: logit[b,t,j] = dot(K[b, sel[b,t,j], :], x[b,t,:]) / 32 - 100
//    One block (256 threads) per (b,t). x row cached in smem. Warp per j.
// ---------------------------------------------------------------------------
__global__ void logits_kernel(const float* __restrict__ x) {
    int bt = blockIdx.x;
    int b  = bt / T_;
    int tid  = threadIdx.x;
    int warp = tid >> 5;
    int lane = tid & 31;

    __shared__ float4 xs[DIM_ / 4];
    const float4* xrow = (const float4*)(x + (size_t)bt * DIM_);
    for (int i = tid; i < DIM_ / 4; i += 256) xs[i] = xrow[i];
    __syncthreads();

    for (int j = warp; j < S_; j += 8) {
        int vsel = g_sel[bt * S_ + j];
        const float4* krow = (const float4*)(g_K + ((size_t)b * V_ + vsel) * DIM_);
        float acc = 0.0f;
        #pragma unroll 4
        for (int i = lane; i < DIM_ / 4; i += 32) {
            float4 a = krow[i];
            float4 c = xs[i];
            acc = fmaf(a.x, c.x, acc);
            acc = fmaf(a.y, c.y, acc);
            acc = fmaf(a.z, c.z, acc);
            acc = fmaf(a.w, c.w, acc);
        }
        #pragma unroll
        for (int off = 16; off > 0; off >>= 1)
            acc += __shfl_down_sync(0xffffffffu, acc, off);
        if (lane == 0)
            g_logit[bt * S_ + j] = acc * (1.0f / 32.0f) - 100.0f;
    }
}

// ---------------------------------------------------------------------------
// 4) Batch-global softmax reduction over T_*S_ = 16384 logits per batch.
// ---------------------------------------------------------------------------
__global__ void softmax_reduce_kernel() {
    int b   = blockIdx.x;
    int tid = threadIdx.x;
    __shared__ float sh[256];
    const float* L = g_logit + (size_t)b * T_ * S_;

    float m = -1e30f;
    for (int i = tid; i < T_ * S_; i += 256) m = fmaxf(m, L[i]);
    sh[tid] = m;  __syncthreads();
    for (int s = 128; s > 0; s >>= 1) {
        if (tid < s) sh[tid] = fmaxf(sh[tid], sh[tid + s]);
        __syncthreads();
    }
    m = sh[0];
    __syncthreads();

    float sum = 0.0f;
    for (int i = tid; i < T_ * S_; i += 256) sum += __expf(L[i] - m);
    sh[tid] = sum;  __syncthreads();
    for (int s = 128; s > 0; s >>= 1) {
        if (tid < s) sh[tid] += sh[tid + s];
        __syncthreads();
    }
    if (tid == 0) { g_red[b * 2] = m; g_red[b * 2 + 1] = sh[0]; }
}

// ---------------------------------------------------------------------------
// 5) Output: out[b,t,:] = x[b,t,:] + sum_j w[b,t,j] * V[b, sel[b,t,j], :]
//    with w = exp(logit - max_b) / sumexp_b. One block per (b,t).
// ---------------------------------------------------------------------------
__global__ void attn_out_kernel(const float* __restrict__ x, float* __restrict__ out) {
    int bt  = blockIdx.x;
    int b   = bt / T_;
    int tid = threadIdx.x;

    __shared__ float w[S_];
    __shared__ int   sidx[S_];
    if (tid < S_) {
        sidx[tid] = g_sel[bt * S_ + tid];
        float m = g_red[b * 2];
        float s = g_red[b * 2 + 1];
        w[tid] = __expf(g_logit[bt * S_ + tid] - m) / s;
    }
    __syncthreads();

    int c = tid * 4;                      // 256 threads * 4 cols = 1024
    const float* vb = g_Vv + (size_t)b * V_ * DIM_;
    float4 acc = make_float4(0.f, 0.f, 0.f, 0.f);
    #pragma unroll 8
    for (int j = 0; j < S_; j++) {
        const float4 vv = *(const float4*)(vb + (size_t)sidx[j] * DIM_ + c);
        float wj = w[j];
        acc.x = fmaf(wj, vv.x, acc.x);
        acc.y = fmaf(wj, vv.y, acc.y);
        acc.z = fmaf(wj, vv.z, acc.z);
        acc.w = fmaf(wj, vv.w, acc.w);
    }
    float4 xr = *(const float4*)(x + (size_t)bt * DIM_ + c);
    acc.x += xr.x; acc.y += xr.y; acc.z += xr.z; acc.w += xr.w;
    *(float4*)(out + (size_t)bt * DIM_ + c) = acc;
}

// ---------------------------------------------------------------------------
// Launch
// ---------------------------------------------------------------------------
extern "C" void kernel_launch(void* const* d_in, const int* in_sizes, int n_in,
                              void* d_out, int out_size)
{
    const float* x      = (const float*)d_in[0];   // (B,T,DIM)
    const float* vision = (const float*)d_in[1];   // (B,V,CV)
    const int*   mask   = (const int*)  d_in[2];   // (B,V,T) bool->4B words
    const float* Wu     = (const float*)d_in[3];   // (CV,DIM)
    const float* bu     = (const float*)d_in[4];   // (DIM,)
    const float* Wk     = (const float*)d_in[5];   // (DIM,DIM)
    const float* Wv     = (const float*)d_in[6];   // (DIM,DIM)
    float* out = (float*)d_out;

    void *pU, *pK, *pV;
    cudaGetSymbolAddress(&pU, g_U);
    cudaGetSymbolAddress(&pK, g_K);
    cudaGetSymbolAddress(&pV, g_Vv);
    float* U  = (float*)pU;
    float* Km = (float*)pK;
    float* Vm = (float*)pV;

    // 1) index selection: one warp per (b,t)
    select_kernel<<<(B_ * T_ + 7) / 8, 256>>>(mask);

    // 2) U = vision @ Wu + bu   : (4096 x 256) @ (256 x 1024)
    sgemm128<<<dim3(DIM_ / 128, (B_ * V_) / 128), 256>>>(vision, Wu, bu, U,
                                                         B_ * V_, DIM_, CV_);
    // 3) K = U @ Wk, V = U @ Wv : (4096 x 1024) @ (1024 x 1024)
    sgemm128<<<dim3(DIM_ / 128, (B_ * V_) / 128), 256>>>(U, Wk, nullptr, Km,
                                                         B_ * V_, DIM_, DIM_);
    sgemm128<<<dim3(DIM_ / 128, (B_ * V_) / 128), 256>>>(U, Wv, nullptr, Vm,
                                                         B_ * V_, DIM_, DIM_);

    // 4) logits, 5) batch softmax reduction, 6) output
    logits_kernel<<<B_ * T_, 256>>>(x);
    softmax_reduce_kernel<<<B_, 256>>>();
    attn_out_kernel<<<B_ * T_, 256>>>(x, out);
}

// round 4
// speedup vs baseline: 3.3438x; 3.3438x over previous
#include <cuda_runtime.h>
#include <cuda_bf16.h>
#include <cstdint>
#include <math.h>

#define B_   4
#define T_   256
#define V_   1024
#define S_   64
#define DIM_ 1024
#define CV_  256

// ---------------------------------------------------------------------------
// Scratch (static device globals)
// ---------------------------------------------------------------------------
__device__ __nv_bfloat16 g_visb[B_ * V_ * CV_];   // vision bf16
__device__ __nv_bfloat16 g_Wut [DIM_ * CV_];      // Wu^T  (N rows, K cols)
__device__ __nv_bfloat16 g_Wkt [DIM_ * DIM_];     // Wk^T
__device__ __nv_bfloat16 g_Wvt [DIM_ * DIM_];     // Wv^T
__device__ __nv_bfloat16 g_Ub  [B_ * V_ * DIM_];  // U  bf16
__device__ __nv_bfloat16 g_Kb  [B_ * V_ * DIM_];  // K  bf16
__device__ __nv_bfloat16 g_Vb  [B_ * V_ * DIM_];  // V  bf16
__device__ int   g_sel  [B_ * T_ * S_];
__device__ float g_logit[B_ * T_ * S_];
__device__ float g_red  [B_ * 2];

// ---------------------------------------------------------------------------
// helpers
// ---------------------------------------------------------------------------
__device__ __forceinline__ uint32_t smem_u32(const void* p) {
    uint32_t a;
    asm("{ .reg .u64 t; cvta.to.shared.u64 t, %1; cvt.u32.u64 %0, t; }"
        : "=r"(a) : "l"(p));
    return a;
}
__device__ __forceinline__ void cp_async16(uint32_t dst, const void* src) {
    asm volatile("cp.async.cg.shared.global [%0], [%1], 16;" :: "r"(dst), "l"(src));
}
#define CP_COMMIT() asm volatile("cp.async.commit_group;" ::: "memory")
#define CP_WAIT(n)  asm volatile("cp.async.wait_group %0;" :: "n"(n) : "memory")

__device__ __forceinline__ void ldmatrix_x4(uint32_t* r, uint32_t addr) {
    asm volatile("ldmatrix.sync.aligned.m8n8.x4.shared.b16 {%0,%1,%2,%3}, [%4];"
                 : "=r"(r[0]), "=r"(r[1]), "=r"(r[2]), "=r"(r[3]) : "r"(addr));
}
__device__ __forceinline__ void mma16816(float* d, const uint32_t* a, const uint32_t* b) {
    asm volatile(
        "mma.sync.aligned.m16n8k16.row.col.f32.bf16.bf16.f32 "
        "{%0,%1,%2,%3},{%4,%5,%6,%7},{%8,%9},{%0,%1,%2,%3};"
        : "+f"(d[0]), "+f"(d[1]), "+f"(d[2]), "+f"(d[3])
        : "r"(a[0]), "r"(a[1]), "r"(a[2]), "r"(a[3]), "r"(b[0]), "r"(b[1]));
}

// ---------------------------------------------------------------------------
// 1) Selection: one warp per (b,t); ballot + prefix-popcount
// ---------------------------------------------------------------------------
__global__ void select_kernel(const int* __restrict__ mask) {
    int warp = (blockIdx.x * blockDim.x + threadIdx.x) >> 5;
    int lane = threadIdx.x & 31;
    if (warp >= B_ * T_) return;
    int b = warp / T_;
    int t = warp % T_;
    const int* m = mask + (size_t)b * V_ * T_ + t;
    int count = 0;
    #pragma unroll 4
    for (int base = 0; base < V_; base += 32) {
        int v = base + lane;
        int val = m[(size_t)v * T_];
        unsigned bal = __ballot_sync(0xffffffffu, val != 0);
        if (val != 0) {
            int pos = count + __popc(bal & ((1u << lane) - 1u));
            if (pos < S_) g_sel[warp * S_ + pos] = v;
        }
        count += __popc(bal);
    }
}

// ---------------------------------------------------------------------------
// 2) fp32 -> bf16 flat convert
// ---------------------------------------------------------------------------
__global__ void convert_bf16(const float4* __restrict__ in,
                             __nv_bfloat162* __restrict__ out, int n4) {
    int i = blockIdx.x * blockDim.x + threadIdx.x;
    if (i < n4) {
        float4 v = in[i];
        out[2 * i]     = __floats2bfloat162_rn(v.x, v.y);
        out[2 * i + 1] = __floats2bfloat162_rn(v.z, v.w);
    }
}

// ---------------------------------------------------------------------------
// 3) Transpose + convert: W (K x N) fp32 -> Wt (N x K) bf16
// ---------------------------------------------------------------------------
__global__ void transpose_convert(const float* __restrict__ W,
                                  __nv_bfloat16* __restrict__ Wt, int K, int N) {
    __shared__ float t[32][33];
    int k0 = blockIdx.y * 32, n0 = blockIdx.x * 32;
    int tx = threadIdx.x, ty = threadIdx.y;   // 32 x 8
    #pragma unroll
    for (int i = 0; i < 32; i += 8)
        t[ty + i][tx] = W[(size_t)(k0 + ty + i) * N + n0 + tx];
    __syncthreads();
    #pragma unroll
    for (int i = 0; i < 32; i += 8)
        Wt[(size_t)(n0 + ty + i) * K + k0 + tx] = __float2bfloat16(t[tx][ty + i]);
}

// ---------------------------------------------------------------------------
// 4) bf16 HMMA GEMM: C[M,N](bf16) = A[M,K] @ Bt[N,K]^T (+bias)
//    CTA tile 128x128, BK=32, 8 warps (warp tile 32x64), cp.async 2-stage.
//    Smem rows padded to 40 bf16 (80B) -> conflict-free ldmatrix.
// ---------------------------------------------------------------------------
#define PAD_ 40

__global__ void __launch_bounds__(256, 1)
gemm_mma(const __nv_bfloat16* __restrict__ A, const __nv_bfloat16* __restrict__ Bt,
         const float* __restrict__ bias, __nv_bfloat16* __restrict__ C,
         int M, int N, int K)
{
    __shared__ __align__(128) __nv_bfloat16 As[2][128][PAD_];
    __shared__ __align__(128) __nv_bfloat16 Bs[2][128][PAD_];
    __shared__ float bsm[128];

    const int tid = threadIdx.x, wid = tid >> 5, lane = tid & 31;
    const int warpM = wid & 3, warpN = wid >> 2;           // 4 x 2 warps
    const int m0 = blockIdx.y * 128, n0 = blockIdx.x * 128;
    const int NC = K >> 5;

    if (bias && tid < 128) bsm[tid] = bias[n0 + tid];

    float d[2][8][4];
    #pragma unroll
    for (int i = 0; i < 2; i++)
        #pragma unroll
        for (int j = 0; j < 8; j++)
            #pragma unroll
            for (int q = 0; q < 4; q++) d[i][j][q] = 0.0f;

    // piece loader: 512 16B pieces per tile; thread handles p = tid, tid+256
    auto load_chunk = [&](int c) {
        int buf = c & 1;
        #pragma unroll
        for (int h = 0; h < 2; h++) {
            int p   = h * 256 + tid;
            int row = p >> 2, pc = p & 3;
            const __nv_bfloat16* ga = A  + (size_t)(m0 + row) * K + c * 32 + pc * 8;
            const __nv_bfloat16* gb = Bt + (size_t)(n0 + row) * K + c * 32 + pc * 8;
            cp_async16(smem_u32(&As[buf][row][pc * 8]), ga);
            cp_async16(smem_u32(&Bs[buf][row][pc * 8]), gb);
        }
        CP_COMMIT();
    };

    load_chunk(0);

    for (int c = 0; c < NC; c++) {
        int buf = c & 1;
        if (c + 1 < NC) { load_chunk(c + 1); CP_WAIT(1); }
        else            { CP_WAIT(0); }
        __syncthreads();

        #pragma unroll
        for (int ks = 0; ks < 2; ks++) {
            uint32_t a[2][4];
            #pragma unroll
            for (int fm = 0; fm < 2; fm++) {
                int r  = warpM * 32 + fm * 16 + (lane & 7) + ((lane >> 3) & 1) * 8;
                int kk = ks * 16 + (lane >> 4) * 8;
                ldmatrix_x4(a[fm], smem_u32(&As[buf][r][kk]));
            }
            uint32_t b[8][2];
            #pragma unroll
            for (int i = 0; i < 4; i++) {
                int r  = warpN * 64 + i * 16 + (lane & 7) + (lane >> 4) * 8;
                int kk = ks * 16 + ((lane >> 3) & 1) * 8;
                uint32_t tmp[4];
                ldmatrix_x4(tmp, smem_u32(&Bs[buf][r][kk]));
                b[2*i][0] = tmp[0]; b[2*i][1] = tmp[1];
                b[2*i+1][0] = tmp[2]; b[2*i+1][1] = tmp[3];
            }
            #pragma unroll
            for (int fm = 0; fm < 2; fm++)
                #pragma unroll
                for (int fn = 0; fn < 8; fn++)
                    mma16816(d[fm][fn], a[fm], b[fn]);
        }
        __syncthreads();
    }

    // Epilogue: frag (fm,fn): rows r0,r0+8; cols col,col+1
    const int mb = m0 + warpM * 32, nb = warpN * 64;
    #pragma unroll
    for (int fm = 0; fm < 2; fm++) {
        #pragma unroll
        for (int fn = 0; fn < 8; fn++) {
            int r0  = mb + fm * 16 + (lane >> 2);
            int col = nb + fn * 8 + 2 * (lane & 3);
            float bz0 = 0.f, bz1 = 0.f;
            if (bias) { bz0 = bsm[col]; bz1 = bsm[col + 1]; }
            __nv_bfloat162* p0 = (__nv_bfloat162*)(C + (size_t)r0 * N + n0 + col);
            __nv_bfloat162* p1 = (__nv_bfloat162*)(C + (size_t)(r0 + 8) * N + n0 + col);
            *p0 = __floats2bfloat162_rn(d[fm][fn][0] + bz0, d[fm][fn][1] + bz1);
            *p1 = __floats2bfloat162_rn(d[fm][fn][2] + bz0, d[fm][fn][3] + bz1);
        }
    }
}

// ---------------------------------------------------------------------------
// 5) Logits: dot(K_bf16[b,sel], x_fp32[b,t]) / 32 - 100
// ---------------------------------------------------------------------------
__global__ void logits_kernel(const float* __restrict__ x) {
    int bt = blockIdx.x;
    int b  = bt / T_;
    int tid = threadIdx.x, warp = tid >> 5, lane = tid & 31;

    __shared__ float xs[DIM_];
    const float4* xr = (const float4*)(x + (size_t)bt * DIM_);
    for (int i = tid; i < DIM_ / 4; i += 256) {
        float4 v = xr[i];
        xs[4*i] = v.x; xs[4*i+1] = v.y; xs[4*i+2] = v.z; xs[4*i+3] = v.w;
    }
    __syncthreads();

    for (int j = warp; j < S_; j += 8) {
        int vs = g_sel[bt * S_ + j];
        const uint4* kr = (const uint4*)(g_Kb + ((size_t)b * V_ + vs) * DIM_);
        float acc = 0.0f;
        #pragma unroll
        for (int i = lane; i < DIM_ / 8; i += 32) {
            uint4 raw = kr[i];
            const __nv_bfloat162* p = (const __nv_bfloat162*)&raw;
            int e = i * 8;
            float2 f0 = __bfloat1622float2(p[0]);
            float2 f1 = __bfloat1622float2(p[1]);
            float2 f2 = __bfloat1622float2(p[2]);
            float2 f3 = __bfloat1622float2(p[3]);
            acc = fmaf(f0.x, xs[e],   acc); acc = fmaf(f0.y, xs[e+1], acc);
            acc = fmaf(f1.x, xs[e+2], acc); acc = fmaf(f1.y, xs[e+3], acc);
            acc = fmaf(f2.x, xs[e+4], acc); acc = fmaf(f2.y, xs[e+5], acc);
            acc = fmaf(f3.x, xs[e+6], acc); acc = fmaf(f3.y, xs[e+7], acc);
        }
        #pragma unroll
        for (int off = 16; off > 0; off >>= 1)
            acc += __shfl_down_sync(0xffffffffu, acc, off);
        if (lane == 0)
            g_logit[bt * S_ + j] = acc * (1.0f / 32.0f) - 100.0f;
    }
}

// ---------------------------------------------------------------------------
// 6) Batch-global softmax reduction
// ---------------------------------------------------------------------------
__global__ void softmax_reduce_kernel() {
    int b = blockIdx.x, tid = threadIdx.x;
    __shared__ float sh[256];
    const float* L = g_logit + (size_t)b * T_ * S_;
    float m = -1e30f;
    for (int i = tid; i < T_ * S_; i += 256) m = fmaxf(m, L[i]);
    sh[tid] = m; __syncthreads();
    for (int s = 128; s > 0; s >>= 1) { if (tid < s) sh[tid] = fmaxf(sh[tid], sh[tid+s]); __syncthreads(); }
    m = sh[0]; __syncthreads();
    float sum = 0.0f;
    for (int i = tid; i < T_ * S_; i += 256) sum += __expf(L[i] - m);
    sh[tid] = sum; __syncthreads();
    for (int s = 128; s > 0; s >>= 1) { if (tid < s) sh[tid] += sh[tid+s]; __syncthreads(); }
    if (tid == 0) { g_red[b*2] = m; g_red[b*2+1] = sh[0]; }
}

// ---------------------------------------------------------------------------
// 7) Output: out = x + sum_j w_j * V_bf16[sel_j]
// ---------------------------------------------------------------------------
__global__ void attn_out_kernel(const float* __restrict__ x, float* __restrict__ out) {
    int bt = blockIdx.x, b = bt / T_, tid = threadIdx.x;
    __shared__ float w[S_];
    __shared__ int   si[S_];
    if (tid < S_) {
        si[tid] = g_sel[bt * S_ + tid];
        w[tid] = __expf(g_logit[bt * S_ + tid] - g_red[b*2]) / g_red[b*2+1];
    }
    __syncthreads();

    float acc[8] = {0,0,0,0,0,0,0,0};
    const __nv_bfloat16* vb = g_Vb + (size_t)b * V_ * DIM_;
    #pragma unroll 4
    for (int j = 0; j < S_; j++) {
        const uint4* rowp = (const uint4*)(vb + (size_t)si[j] * DIM_);
        uint4 raw = rowp[tid];
        const __nv_bfloat162* p = (const __nv_bfloat162*)&raw;
        float wj = w[j];
        #pragma unroll
        for (int q = 0; q < 4; q++) {
            float2 f = __bfloat1622float2(p[q]);
            acc[2*q]   = fmaf(wj, f.x, acc[2*q]);
            acc[2*q+1] = fmaf(wj, f.y, acc[2*q+1]);
        }
    }
    int c = tid * 8;
    const float4* xr = (const float4*)(x + (size_t)bt * DIM_ + c);
    float4 x0 = xr[0], x1 = xr[1];
    float4 o0 = make_float4(acc[0]+x0.x, acc[1]+x0.y, acc[2]+x0.z, acc[3]+x0.w);
    float4 o1 = make_float4(acc[4]+x1.x, acc[5]+x1.y, acc[6]+x1.z, acc[7]+x1.w);
    float4* op = (float4*)(out + (size_t)bt * DIM_ + c);
    op[0] = o0; op[1] = o1;
}

// ---------------------------------------------------------------------------
// Launch
// ---------------------------------------------------------------------------
extern "C" void kernel_launch(void* const* d_in, const int* in_sizes, int n_in,
                              void* d_out, int out_size)
{
    const float* x      = (const float*)d_in[0];
    const float* vision = (const float*)d_in[1];
    const int*   mask   = (const int*)  d_in[2];
    const float* Wu     = (const float*)d_in[3];
    const float* bu     = (const float*)d_in[4];
    const float* Wk     = (const float*)d_in[5];
    const float* Wv     = (const float*)d_in[6];
    float* out = (float*)d_out;

    void *pvb, *pwu, *pwk, *pwv, *pu, *pk, *pv;
    cudaGetSymbolAddress(&pvb, g_visb);
    cudaGetSymbolAddress(&pwu, g_Wut);
    cudaGetSymbolAddress(&pwk, g_Wkt);
    cudaGetSymbolAddress(&pwv, g_Wvt);
    cudaGetSymbolAddress(&pu,  g_Ub);
    cudaGetSymbolAddress(&pk,  g_Kb);
    cudaGetSymbolAddress(&pv,  g_Vb);

    select_kernel<<<(B_ * T_ + 7) / 8, 256>>>(mask);

    convert_bf16<<<(B_*V_*CV_/4 + 255)/256, 256>>>((const float4*)vision,
                                                   (__nv_bfloat162*)pvb, B_*V_*CV_/4);
    transpose_convert<<<dim3(DIM_/32, CV_/32),  dim3(32,8)>>>(Wu, (__nv_bfloat16*)pwu, CV_,  DIM_);
    transpose_convert<<<dim3(DIM_/32, DIM_/32), dim3(32,8)>>>(Wk, (__nv_bfloat16*)pwk, DIM_, DIM_);
    transpose_convert<<<dim3(DIM_/32, DIM_/32), dim3(32,8)>>>(Wv, (__nv_bfloat16*)pwv, DIM_, DIM_);

    dim3 ggrid(DIM_ / 128, (B_ * V_) / 128);   // (8, 32)
    gemm_mma<<<ggrid, 256>>>((const __nv_bfloat16*)pvb, (const __nv_bfloat16*)pwu,
                             bu, (__nv_bfloat16*)pu, B_*V_, DIM_, CV_);
    gemm_mma<<<ggrid, 256>>>((const __nv_bfloat16*)pu, (const __nv_bfloat16*)pwk,
                             nullptr, (__nv_bfloat16*)pk, B_*V_, DIM_, DIM_);
    gemm_mma<<<ggrid, 256>>>((const __nv_bfloat16*)pu, (const __nv_bfloat16*)pwv,
                             nullptr, (__nv_bfloat16*)pv, B_*V_, DIM_, DIM_);

    logits_kernel<<<B_ * T_, 256>>>(x);
    softmax_reduce_kernel<<<B_, 256>>>();
    attn_out_kernel<<<B_ * T_, 128>>>(x, out);
}

// round 5
// speedup vs baseline: 4.3686x; 1.3065x over previous
#include <cuda_runtime.h>
#include <cuda_bf16.h>
#include <cstdint>
#include <math.h>

#define B_   4
#define T_   256
#define V_   1024
#define S_   64
#define DIM_ 1024
#define CV_  256

// ---------------------------------------------------------------------------
// Scratch (static device globals)
// ---------------------------------------------------------------------------
__device__ __nv_bfloat16 g_visb[B_ * V_ * CV_];   // vision bf16 (A of KV gemm)
__device__ __nv_bfloat16 g_Wub [CV_ * DIM_];      // Wu  bf16 (row-major 256x1024)
__device__ __nv_bfloat16 g_Wkb [DIM_ * DIM_];     // Wk  bf16 (row-major KxN)
__device__ __nv_bfloat16 g_Wvb [DIM_ * DIM_];     // Wv  bf16
__device__ __nv_bfloat16 g_Wuk [CV_ * DIM_];      // Wu@Wk bf16 (256x1024)
__device__ __nv_bfloat16 g_Wuv [CV_ * DIM_];      // Wu@Wv bf16
__device__ float         g_buk [DIM_];            // bu@Wk
__device__ float         g_buv [DIM_];            // bu@Wv
__device__ __nv_bfloat16 g_Kb  [B_ * V_ * DIM_];  // K bf16
__device__ __nv_bfloat16 g_Vb  [B_ * V_ * DIM_];  // V bf16
__device__ int   g_sel  [B_ * T_ * S_];
__device__ float g_logit[B_ * T_ * S_];
__device__ float g_red  [B_ * 2];

// ---------------------------------------------------------------------------
// helpers
// ---------------------------------------------------------------------------
__device__ __forceinline__ uint32_t smem_u32(const void* p) {
    uint32_t a;
    asm("{ .reg .u64 t; cvta.to.shared.u64 t, %1; cvt.u32.u64 %0, t; }"
        : "=r"(a) : "l"(p));
    return a;
}
__device__ __forceinline__ void cp_async16(uint32_t dst, const void* src) {
    asm volatile("cp.async.cg.shared.global [%0], [%1], 16;" :: "r"(dst), "l"(src));
}
#define CP_COMMIT() asm volatile("cp.async.commit_group;" ::: "memory")
#define CP_WAIT(n)  asm volatile("cp.async.wait_group %0;" :: "n"(n) : "memory")

__device__ __forceinline__ void ldmatrix_x4(uint32_t* r, uint32_t addr) {
    asm volatile("ldmatrix.sync.aligned.m8n8.x4.shared.b16 {%0,%1,%2,%3}, [%4];"
                 : "=r"(r[0]), "=r"(r[1]), "=r"(r[2]), "=r"(r[3]) : "r"(addr));
}
__device__ __forceinline__ void ldmatrix_x4_trans(uint32_t* r, uint32_t addr) {
    asm volatile("ldmatrix.sync.aligned.m8n8.x4.trans.shared.b16 {%0,%1,%2,%3}, [%4];"
                 : "=r"(r[0]), "=r"(r[1]), "=r"(r[2]), "=r"(r[3]) : "r"(addr));
}
__device__ __forceinline__ void mma16816(float* d, const uint32_t* a, const uint32_t* b) {
    asm volatile(
        "mma.sync.aligned.m16n8k16.row.col.f32.bf16.bf16.f32 "
        "{%0,%1,%2,%3},{%4,%5,%6,%7},{%8,%9},{%0,%1,%2,%3};"
        : "+f"(d[0]), "+f"(d[1]), "+f"(d[2]), "+f"(d[3])
        : "r"(a[0]), "r"(a[1]), "r"(a[2]), "r"(a[3]), "r"(b[0]), "r"(b[1]));
}

// ---------------------------------------------------------------------------
// 1) Selection: one warp per (b,t); ballot + prefix-popcount
// ---------------------------------------------------------------------------
__global__ void select_kernel(const int* __restrict__ mask) {
    int warp = (blockIdx.x * blockDim.x + threadIdx.x) >> 5;
    int lane = threadIdx.x & 31;
    if (warp >= B_ * T_) return;
    int b = warp / T_;
    int t = warp % T_;
    const int* m = mask + (size_t)b * V_ * T_ + t;
    int count = 0;
    #pragma unroll 4
    for (int base = 0; base < V_; base += 32) {
        int v = base + lane;
        int val = m[(size_t)v * T_];
        unsigned bal = __ballot_sync(0xffffffffu, val != 0);
        if (val != 0) {
            int pos = count + __popc(bal & ((1u << lane) - 1u));
            if (pos < S_) g_sel[warp * S_ + pos] = v;
        }
        count += __popc(bal);
    }
}

// ---------------------------------------------------------------------------
// 2) Fused fp32 -> bf16 flat converts: 4 segments via blockIdx.y
// ---------------------------------------------------------------------------
__global__ void convert4_bf16(const float4* s0, __nv_bfloat162* o0, int n0,
                              const float4* s1, __nv_bfloat162* o1, int n1,
                              const float4* s2, __nv_bfloat162* o2, int n2,
                              const float4* s3, __nv_bfloat162* o3, int n3) {
    const float4* s;  __nv_bfloat162* o;  int n;
    switch (blockIdx.y) {
        case 0: s = s0; o = o0; n = n0; break;
        case 1: s = s1; o = o1; n = n1; break;
        case 2: s = s2; o = o2; n = n2; break;
        default: s = s3; o = o3; n = n3; break;
    }
    int i = blockIdx.x * blockDim.x + threadIdx.x;
    if (i < n) {
        float4 v = s[i];
        o[2 * i]     = __floats2bfloat162_rn(v.x, v.y);
        o[2 * i + 1] = __floats2bfloat162_rn(v.z, v.w);
    }
}

// ---------------------------------------------------------------------------
// 3) buk[n] = sum_c bu[c] * W[c][n]   (fp32; blockIdx.y selects Wk / Wv)
// ---------------------------------------------------------------------------
__global__ void bias_fold_kernel(const float* __restrict__ bu,
                                 const float* __restrict__ Wk,
                                 const float* __restrict__ Wv) {
    const float* W = blockIdx.y ? Wv : Wk;
    float* outp    = blockIdx.y ? g_buv : g_buk;
    int n = blockIdx.x * blockDim.x + threadIdx.x;
    float acc = 0.0f;
    #pragma unroll 8
    for (int c = 0; c < DIM_; c++)
        acc = fmaf(bu[c], W[(size_t)c * DIM_ + n], acc);
    outp[n] = acc;
}

// ---------------------------------------------------------------------------
// 4) bf16 HMMA GEMM: C[M,N](bf16) = A[M,K] @ B[K,N] (+bias[N])
//    A row-major, B row-major (ldmatrix.trans). CTA tile 128x128, BK=32.
//    blockIdx.z selects (B0,bias0,C0) vs (B1,bias1,C1) — A shared.
// ---------------------------------------------------------------------------
#define APAD 8
#define BPAD 8

__global__ void __launch_bounds__(256)
gemm_tn(const __nv_bfloat16* __restrict__ A,
        const __nv_bfloat16* __restrict__ B0, const __nv_bfloat16* __restrict__ B1,
        const float* __restrict__ bias0, const float* __restrict__ bias1,
        __nv_bfloat16* __restrict__ C0, __nv_bfloat16* __restrict__ C1,
        int M, int N, int K)
{
    const __nv_bfloat16* Bm = blockIdx.z ? B1 : B0;
    const float* bias       = blockIdx.z ? bias1 : bias0;
    __nv_bfloat16* C        = blockIdx.z ? C1 : C0;

    __shared__ __align__(128) __nv_bfloat16 As[2][128][32 + APAD];
    __shared__ __align__(128) __nv_bfloat16 Bs[2][32][128 + BPAD];
    __shared__ float bsm[128];

    const int tid = threadIdx.x, wid = tid >> 5, lane = tid & 31;
    const int warpM = wid & 3, warpN = wid >> 2;           // 4 x 2 warps
    const int m0 = blockIdx.y * 128, n0 = blockIdx.x * 128;
    const int NC = K >> 5;

    if (bias && tid < 128) bsm[tid] = bias[n0 + tid];

    float d[2][8][4];
    #pragma unroll
    for (int i = 0; i < 2; i++)
        #pragma unroll
        for (int j = 0; j < 8; j++)
            #pragma unroll
            for (int q = 0; q < 4; q++) d[i][j][q] = 0.0f;

    // A tile: 128 rows x 32 cols = 512 x 16B ; B tile: 32 rows x 128 cols = 512 x 16B
    auto load_chunk = [&](int c) {
        int buf = c & 1;
        #pragma unroll
        for (int h = 0; h < 2; h++) {
            int p = h * 256 + tid;
            {   // A piece
                int row = p >> 2, pc = p & 3;
                cp_async16(smem_u32(&As[buf][row][pc * 8]),
                           A + (size_t)(m0 + row) * K + c * 32 + pc * 8);
            }
            {   // B piece
                int row = p >> 4, pc = p & 15;
                cp_async16(smem_u32(&Bs[buf][row][pc * 8]),
                           Bm + (size_t)(c * 32 + row) * N + n0 + pc * 8);
            }
        }
        CP_COMMIT();
    };

    load_chunk(0);

    for (int c = 0; c < NC; c++) {
        int buf = c & 1;
        if (c + 1 < NC) { load_chunk(c + 1); CP_WAIT(1); }
        else            { CP_WAIT(0); }
        __syncthreads();

        #pragma unroll
        for (int ks = 0; ks < 2; ks++) {
            uint32_t a[2][4];
            #pragma unroll
            for (int fm = 0; fm < 2; fm++) {
                int r  = warpM * 32 + fm * 16 + (lane & 7) + ((lane >> 3) & 1) * 8;
                int kk = ks * 16 + (lane >> 4) * 8;
                ldmatrix_x4(a[fm], smem_u32(&As[buf][r][kk]));
            }
            uint32_t b[8][2];
            #pragma unroll
            for (int i = 0; i < 4; i++) {
                int kk = ks * 16 + (lane & 15);
                int nn = warpN * 64 + i * 16 + (lane >> 4) * 8;
                uint32_t tmp[4];
                ldmatrix_x4_trans(tmp, smem_u32(&Bs[buf][kk][nn]));
                b[2*i][0]   = tmp[0]; b[2*i][1]   = tmp[1];
                b[2*i+1][0] = tmp[2]; b[2*i+1][1] = tmp[3];
            }
            #pragma unroll
            for (int fm = 0; fm < 2; fm++)
                #pragma unroll
                for (int fn = 0; fn < 8; fn++)
                    mma16816(d[fm][fn], a[fm], b[fn]);
        }
        __syncthreads();
    }

    const int mb = m0 + warpM * 32, nb = warpN * 64;
    #pragma unroll
    for (int fm = 0; fm < 2; fm++) {
        #pragma unroll
        for (int fn = 0; fn < 8; fn++) {
            int r0  = mb + fm * 16 + (lane >> 2);
            int col = nb + fn * 8 + 2 * (lane & 3);
            float bz0 = 0.f, bz1 = 0.f;
            if (bias) { bz0 = bsm[col]; bz1 = bsm[col + 1]; }
            __nv_bfloat162* p0 = (__nv_bfloat162*)(C + (size_t)r0 * N + n0 + col);
            __nv_bfloat162* p1 = (__nv_bfloat162*)(C + (size_t)(r0 + 8) * N + n0 + col);
            *p0 = __floats2bfloat162_rn(d[fm][fn][0] + bz0, d[fm][fn][1] + bz1);
            *p1 = __floats2bfloat162_rn(d[fm][fn][2] + bz0, d[fm][fn][3] + bz1);
        }
    }
}

// ---------------------------------------------------------------------------
// 5) Logits: dot(K_bf16[b,sel], x_fp32[b,t]) / 32 - 100
// ---------------------------------------------------------------------------
__global__ void logits_kernel(const float* __restrict__ x) {
    int bt = blockIdx.x;
    int b  = bt / T_;
    int tid = threadIdx.x, warp = tid >> 5, lane = tid & 31;

    __shared__ float xs[DIM_];
    const float4* xr = (const float4*)(x + (size_t)bt * DIM_);
    for (int i = tid; i < DIM_ / 4; i += 256) {
        float4 v = xr[i];
        xs[4*i] = v.x; xs[4*i+1] = v.y; xs[4*i+2] = v.z; xs[4*i+3] = v.w;
    }
    __syncthreads();

    for (int j = warp; j < S_; j += 8) {
        int vs = g_sel[bt * S_ + j];
        const uint4* kr = (const uint4*)(g_Kb + ((size_t)b * V_ + vs) * DIM_);
        float acc = 0.0f;
        #pragma unroll
        for (int i = lane; i < DIM_ / 8; i += 32) {
            uint4 raw = kr[i];
            const __nv_bfloat162* p = (const __nv_bfloat162*)&raw;
            int e = i * 8;
            float2 f0 = __bfloat1622float2(p[0]);
            float2 f1 = __bfloat1622float2(p[1]);
            float2 f2 = __bfloat1622float2(p[2]);
            float2 f3 = __bfloat1622float2(p[3]);
            acc = fmaf(f0.x, xs[e],   acc); acc = fmaf(f0.y, xs[e+1], acc);
            acc = fmaf(f1.x, xs[e+2], acc); acc = fmaf(f1.y, xs[e+3], acc);
            acc = fmaf(f2.x, xs[e+4], acc); acc = fmaf(f2.y, xs[e+5], acc);
            acc = fmaf(f3.x, xs[e+6], acc); acc = fmaf(f3.y, xs[e+7], acc);
        }
        #pragma unroll
        for (int off = 16; off > 0; off >>= 1)
            acc += __shfl_down_sync(0xffffffffu, acc, off);
        if (lane == 0)
            g_logit[bt * S_ + j] = acc * (1.0f / 32.0f) - 100.0f;
    }
}

// ---------------------------------------------------------------------------
// 6) Batch-global softmax reduction
// ---------------------------------------------------------------------------
__global__ void softmax_reduce_kernel() {
    int b = blockIdx.x, tid = threadIdx.x;
    __shared__ float sh[256];
    const float* L = g_logit + (size_t)b * T_ * S_;
    float m = -1e30f;
    for (int i = tid; i < T_ * S_; i += 256) m = fmaxf(m, L[i]);
    sh[tid] = m; __syncthreads();
    for (int s = 128; s > 0; s >>= 1) { if (tid < s) sh[tid] = fmaxf(sh[tid], sh[tid+s]); __syncthreads(); }
    m = sh[0]; __syncthreads();
    float sum = 0.0f;
    for (int i = tid; i < T_ * S_; i += 256) sum += __expf(L[i] - m);
    sh[tid] = sum; __syncthreads();
    for (int s = 128; s > 0; s >>= 1) { if (tid < s) sh[tid] += sh[tid+s]; __syncthreads(); }
    if (tid == 0) { g_red[b*2] = m; g_red[b*2+1] = sh[0]; }
}

// ---------------------------------------------------------------------------
// 7) Output: out = x + sum_j w_j * V_bf16[sel_j]
// ---------------------------------------------------------------------------
__global__ void attn_out_kernel(const float* __restrict__ x, float* __restrict__ out) {
    int bt = blockIdx.x, b = bt / T_, tid = threadIdx.x;
    __shared__ float w[S_];
    __shared__ int   si[S_];
    if (tid < S_) {
        si[tid] = g_sel[bt * S_ + tid];
        w[tid] = __expf(g_logit[bt * S_ + tid] - g_red[b*2]) / g_red[b*2+1];
    }
    __syncthreads();

    float acc[8] = {0,0,0,0,0,0,0,0};
    const __nv_bfloat16* vb = g_Vb + (size_t)b * V_ * DIM_;
    #pragma unroll 4
    for (int j = 0; j < S_; j++) {
        const uint4* rowp = (const uint4*)(vb + (size_t)si[j] * DIM_);
        uint4 raw = rowp[tid];
        const __nv_bfloat162* p = (const __nv_bfloat162*)&raw;
        float wj = w[j];
        #pragma unroll
        for (int q = 0; q < 4; q++) {
            float2 f = __bfloat1622float2(p[q]);
            acc[2*q]   = fmaf(wj, f.x, acc[2*q]);
            acc[2*q+1] = fmaf(wj, f.y, acc[2*q+1]);
        }
    }
    int c = tid * 8;
    const float4* xr = (const float4*)(x + (size_t)bt * DIM_ + c);
    float4 x0 = xr[0], x1 = xr[1];
    float4 o0 = make_float4(acc[0]+x0.x, acc[1]+x0.y, acc[2]+x0.z, acc[3]+x0.w);
    float4 o1 = make_float4(acc[4]+x1.x, acc[5]+x1.y, acc[6]+x1.z, acc[7]+x1.w);
    float4* op = (float4*)(out + (size_t)bt * DIM_ + c);
    op[0] = o0; op[1] = o1;
}

// ---------------------------------------------------------------------------
// Launch
// ---------------------------------------------------------------------------
extern "C" void kernel_launch(void* const* d_in, const int* in_sizes, int n_in,
                              void* d_out, int out_size)
{
    const float* x      = (const float*)d_in[0];
    const float* vision = (const float*)d_in[1];
    const int*   mask   = (const int*)  d_in[2];
    const float* Wu     = (const float*)d_in[3];
    const float* bu     = (const float*)d_in[4];
    const float* Wk     = (const float*)d_in[5];
    const float* Wv     = (const float*)d_in[6];
    float* out = (float*)d_out;

    void *pvb, *pwu, *pwk, *pwv, *puk, *puv, *pbk, *pbv, *pk, *pv;
    cudaGetSymbolAddress(&pvb, g_visb);
    cudaGetSymbolAddress(&pwu, g_Wub);
    cudaGetSymbolAddress(&pwk, g_Wkb);
    cudaGetSymbolAddress(&pwv, g_Wvb);
    cudaGetSymbolAddress(&puk, g_Wuk);
    cudaGetSymbolAddress(&puv, g_Wuv);
    cudaGetSymbolAddress(&pbk, g_buk);
    cudaGetSymbolAddress(&pbv, g_buv);
    cudaGetSymbolAddress(&pk,  g_Kb);
    cudaGetSymbolAddress(&pv,  g_Vb);

    select_kernel<<<(B_ * T_ + 7) / 8, 256>>>(mask);

    // fp32 -> bf16 flat converts: vision, Wu, Wk, Wv
    const int n_vis = B_*V_*CV_/4, n_wu = CV_*DIM_/4, n_w = DIM_*DIM_/4;
    convert4_bf16<<<dim3((n_w + 255)/256, 4), 256>>>(
        (const float4*)vision, (__nv_bfloat162*)pvb, n_vis,
        (const float4*)Wu,     (__nv_bfloat162*)pwu, n_wu,
        (const float4*)Wk,     (__nv_bfloat162*)pwk, n_w,
        (const float4*)Wv,     (__nv_bfloat162*)pwv, n_w);

    // buk = bu@Wk, buv = bu@Wv
    bias_fold_kernel<<<dim3(DIM_/256, 2), 256>>>(bu, Wk, Wv);

    // Wuk = Wu@Wk, Wuv = Wu@Wv   (M=256, N=1024, K=1024; z picks Wk/Wv)
    gemm_tn<<<dim3(DIM_/128, CV_/128, 2), 256>>>(
        (const __nv_bfloat16*)pwu,
        (const __nv_bfloat16*)pwk, (const __nv_bfloat16*)pwv,
        nullptr, nullptr,
        (__nv_bfloat16*)puk, (__nv_bfloat16*)puv,
        CV_, DIM_, DIM_);

    // K = vision@Wuk + buk, V = vision@Wuv + buv  (M=4096, N=1024, K=256)
    gemm_tn<<<dim3(DIM_/128, (B_*V_)/128, 2), 256>>>(
        (const __nv_bfloat16*)pvb,
        (const __nv_bfloat16*)puk, (const __nv_bfloat16*)puv,
        (const float*)pbk, (const float*)pbv,
        (__nv_bfloat16*)pk, (__nv_bfloat16*)pv,
        B_*V_, DIM_, CV_);

    logits_kernel<<<B_ * T_, 256>>>(x);
    softmax_reduce_kernel<<<B_, 256>>>();
    attn_out_kernel<<<B_ * T_, 128>>>(x, out);
}

// round 6
// speedup vs baseline: 5.8984x; 1.3502x over previous
#include <cuda_runtime.h>
#include <cuda_bf16.h>
#include <cstdint>
#include <math.h>

#define B_   4
#define T_   256
#define V_   1024
#define S_   64
#define DIM_ 1024
#define CV_  256
#define SPLITS 8
#define SK_  (DIM_ / SPLITS)     // 128 K per split

// ---------------------------------------------------------------------------
// Scratch (static device globals)
// ---------------------------------------------------------------------------
__device__ __nv_bfloat16 g_visb[B_ * V_ * CV_];   // vision bf16
__device__ __nv_bfloat16 g_Wub [CV_ * DIM_];      // Wu  bf16
__device__ __nv_bfloat16 g_Wkb [DIM_ * DIM_];     // Wk  bf16
__device__ __nv_bfloat16 g_Wvb [DIM_ * DIM_];     // Wv  bf16
__device__ __nv_bfloat16 g_Wuk [CV_ * DIM_];      // Wu@Wk bf16
__device__ __nv_bfloat16 g_Wuv [CV_ * DIM_];      // Wu@Wv bf16
__device__ float         g_part[2 * SPLITS][CV_ * DIM_];  // split-K partials (16MB)
__device__ float         g_buk [DIM_];
__device__ float         g_buv [DIM_];
__device__ __nv_bfloat16 g_Kb  [B_ * V_ * DIM_];
__device__ __nv_bfloat16 g_Vb  [B_ * V_ * DIM_];
__device__ int    g_sel  [B_ * T_ * S_];
__device__ float  g_logit[B_ * T_ * S_];
__device__ float2 g_ms   [B_ * T_];               // per-(b,t) local (max, sumexp)
__device__ float  g_red  [B_ * 2];                // per-batch (max, sumexp)

// ---------------------------------------------------------------------------
// helpers
// ---------------------------------------------------------------------------
__device__ __forceinline__ uint32_t smem_u32(const void* p) {
    uint32_t a;
    asm("{ .reg .u64 t; cvta.to.shared.u64 t, %1; cvt.u32.u64 %0, t; }"
        : "=r"(a) : "l"(p));
    return a;
}
__device__ __forceinline__ void cp_async16(uint32_t dst, const void* src) {
    asm volatile("cp.async.cg.shared.global [%0], [%1], 16;" :: "r"(dst), "l"(src));
}
#define CP_COMMIT() asm volatile("cp.async.commit_group;" ::: "memory")
#define CP_WAIT(n)  asm volatile("cp.async.wait_group %0;" :: "n"(n) : "memory")

__device__ __forceinline__ void ldmatrix_x4(uint32_t* r, uint32_t addr) {
    asm volatile("ldmatrix.sync.aligned.m8n8.x4.shared.b16 {%0,%1,%2,%3}, [%4];"
                 : "=r"(r[0]), "=r"(r[1]), "=r"(r[2]), "=r"(r[3]) : "r"(addr));
}
__device__ __forceinline__ void ldmatrix_x4_trans(uint32_t* r, uint32_t addr) {
    asm volatile("ldmatrix.sync.aligned.m8n8.x4.trans.shared.b16 {%0,%1,%2,%3}, [%4];"
                 : "=r"(r[0]), "=r"(r[1]), "=r"(r[2]), "=r"(r[3]) : "r"(addr));
}
__device__ __forceinline__ void mma16816(float* d, const uint32_t* a, const uint32_t* b) {
    asm volatile(
        "mma.sync.aligned.m16n8k16.row.col.f32.bf16.bf16.f32 "
        "{%0,%1,%2,%3},{%4,%5,%6,%7},{%8,%9},{%0,%1,%2,%3};"
        : "+f"(d[0]), "+f"(d[1]), "+f"(d[2]), "+f"(d[3])
        : "r"(a[0]), "r"(a[1]), "r"(a[2]), "r"(a[3]), "r"(b[0]), "r"(b[1]));
}

#define APAD 8
#define BPAD 8

// ---------------------------------------------------------------------------
// 1) Selection
// ---------------------------------------------------------------------------
__global__ void select_kernel(const int* __restrict__ mask) {
    int warp = (blockIdx.x * blockDim.x + threadIdx.x) >> 5;
    int lane = threadIdx.x & 31;
    if (warp >= B_ * T_) return;
    int b = warp / T_;
    int t = warp % T_;
    const int* m = mask + (size_t)b * V_ * T_ + t;
    int count = 0;
    #pragma unroll 4
    for (int base = 0; base < V_; base += 32) {
        int v = base + lane;
        int val = m[(size_t)v * T_];
        unsigned bal = __ballot_sync(0xffffffffu, val != 0);
        if (val != 0) {
            int pos = count + __popc(bal & ((1u << lane) - 1u));
            if (pos < S_) g_sel[warp * S_ + pos] = v;
        }
        count += __popc(bal);
    }
}

// ---------------------------------------------------------------------------
// 2) Fused fp32 -> bf16 converts (4 segments)
// ---------------------------------------------------------------------------
__global__ void convert4_bf16(const float4* s0, __nv_bfloat162* o0, int n0,
                              const float4* s1, __nv_bfloat162* o1, int n1,
                              const float4* s2, __nv_bfloat162* o2, int n2,
                              const float4* s3, __nv_bfloat162* o3, int n3) {
    const float4* s;  __nv_bfloat162* o;  int n;
    switch (blockIdx.y) {
        case 0: s = s0; o = o0; n = n0; break;
        case 1: s = s1; o = o1; n = n1; break;
        case 2: s = s2; o = o2; n = n2; break;
        default: s = s3; o = o3; n = n3; break;
    }
    int i = blockIdx.x * blockDim.x + threadIdx.x;
    if (i < n) {
        float4 v = s[i];
        o[2 * i]     = __floats2bfloat162_rn(v.x, v.y);
        o[2 * i + 1] = __floats2bfloat162_rn(v.z, v.w);
    }
}

// ---------------------------------------------------------------------------
// 3) bias fold: buk[n] = sum_c bu[c]*W[c][n]; 4-way K-split per block
// ---------------------------------------------------------------------------
__global__ void bias_fold_kernel(const float* __restrict__ bu,
                                 const float* __restrict__ Wk,
                                 const float* __restrict__ Wv) {
    const float* W = blockIdx.y ? Wv : Wk;
    float* outp    = blockIdx.y ? g_buv : g_buk;
    int tx = threadIdx.x & 63, ty = threadIdx.x >> 6;   // 64 cols x 4 K-groups
    int n = blockIdx.x * 64 + tx;
    __shared__ float partial[4][64];
    float acc = 0.0f;
    int c0 = ty * 256;
    #pragma unroll 8
    for (int c = c0; c < c0 + 256; c++)
        acc = fmaf(bu[c], W[(size_t)c * DIM_ + n], acc);
    partial[ty][tx] = acc;
    __syncthreads();
    if (ty == 0)
        outp[n] = partial[0][tx] + partial[1][tx] + partial[2][tx] + partial[3][tx];
}

// ---------------------------------------------------------------------------
// 4a) Split-K GEMM for Wuk/Wuv: fp32 partials.
//     grid (N/128, M/128, 2*SPLITS); z: kv = z&1, split = z>>1.
// ---------------------------------------------------------------------------
__global__ void __launch_bounds__(256)
gemm_splitk(const __nv_bfloat16* __restrict__ A,
            const __nv_bfloat16* __restrict__ B0, const __nv_bfloat16* __restrict__ B1)
{
    const int kv = blockIdx.z & 1, split = blockIdx.z >> 1;
    const __nv_bfloat16* Bm = kv ? B1 : B0;
    float* Cp = g_part[kv * SPLITS + split];
    const int M = CV_, N = DIM_, K = DIM_;
    const int kbase = split * SK_;

    __shared__ __align__(128) __nv_bfloat16 As[2][128][32 + APAD];
    __shared__ __align__(128) __nv_bfloat16 Bs[2][32][128 + BPAD];

    const int tid = threadIdx.x, wid = tid >> 5, lane = tid & 31;
    const int warpM = wid & 3, warpN = wid >> 2;
    const int m0 = blockIdx.y * 128, n0 = blockIdx.x * 128;
    const int NC = SK_ >> 5;                       // 4 chunks

    float d[2][8][4];
    #pragma unroll
    for (int i = 0; i < 2; i++)
        #pragma unroll
        for (int j = 0; j < 8; j++)
            #pragma unroll
            for (int q = 0; q < 4; q++) d[i][j][q] = 0.0f;

    auto load_chunk = [&](int c) {
        int buf = c & 1;
        #pragma unroll
        for (int h = 0; h < 2; h++) {
            int p = h * 256 + tid;
            {
                int row = p >> 2, pc = p & 3;
                cp_async16(smem_u32(&As[buf][row][pc * 8]),
                           A + (size_t)(m0 + row) * K + kbase + c * 32 + pc * 8);
            }
            {
                int row = p >> 4, pc = p & 15;
                cp_async16(smem_u32(&Bs[buf][row][pc * 8]),
                           Bm + (size_t)(kbase + c * 32 + row) * N + n0 + pc * 8);
            }
        }
        CP_COMMIT();
    };

    load_chunk(0);

    for (int c = 0; c < NC; c++) {
        int buf = c & 1;
        if (c + 1 < NC) { load_chunk(c + 1); CP_WAIT(1); }
        else            { CP_WAIT(0); }
        __syncthreads();

        #pragma unroll
        for (int ks = 0; ks < 2; ks++) {
            uint32_t a[2][4];
            #pragma unroll
            for (int fm = 0; fm < 2; fm++) {
                int r  = warpM * 32 + fm * 16 + (lane & 7) + ((lane >> 3) & 1) * 8;
                int kk = ks * 16 + (lane >> 4) * 8;
                ldmatrix_x4(a[fm], smem_u32(&As[buf][r][kk]));
            }
            uint32_t b[8][2];
            #pragma unroll
            for (int i = 0; i < 4; i++) {
                int kk = ks * 16 + (lane & 15);
                int nn = warpN * 64 + i * 16 + (lane >> 4) * 8;
                uint32_t tmp[4];
                ldmatrix_x4_trans(tmp, smem_u32(&Bs[buf][kk][nn]));
                b[2*i][0]   = tmp[0]; b[2*i][1]   = tmp[1];
                b[2*i+1][0] = tmp[2]; b[2*i+1][1] = tmp[3];
            }
            #pragma unroll
            for (int fm = 0; fm < 2; fm++)
                #pragma unroll
                for (int fn = 0; fn < 8; fn++)
                    mma16816(d[fm][fn], a[fm], b[fn]);
        }
        __syncthreads();
    }

    const int mb = m0 + warpM * 32, nb = warpN * 64;
    #pragma unroll
    for (int fm = 0; fm < 2; fm++) {
        #pragma unroll
        for (int fn = 0; fn < 8; fn++) {
            int r0  = mb + fm * 16 + (lane >> 2);
            int col = n0 + nb + fn * 8 + 2 * (lane & 3);
            *(float2*)(Cp + (size_t)r0 * N + col)       = make_float2(d[fm][fn][0], d[fm][fn][1]);
            *(float2*)(Cp + (size_t)(r0 + 8) * N + col) = make_float2(d[fm][fn][2], d[fm][fn][3]);
        }
    }
}

// 4b) Reduce split-K partials -> bf16 Wuk / Wuv
__global__ void reduce_splitk() {
    int i  = blockIdx.x * blockDim.x + threadIdx.x;   // float4 index
    int kv = blockIdx.y;
    float4 acc = make_float4(0.f, 0.f, 0.f, 0.f);
    #pragma unroll
    for (int s = 0; s < SPLITS; s++) {
        float4 p = ((const float4*)g_part[kv * SPLITS + s])[i];
        acc.x += p.x; acc.y += p.y; acc.z += p.z; acc.w += p.w;
    }
    __nv_bfloat162* o = (__nv_bfloat162*)(kv ? g_Wuv : g_Wuk);
    o[2 * i]     = __floats2bfloat162_rn(acc.x, acc.y);
    o[2 * i + 1] = __floats2bfloat162_rn(acc.z, acc.w);
}

// ---------------------------------------------------------------------------
// 4c) KV GEMM: C = A @ B (+bias); z selects (Wuk,buk,K) / (Wuv,buv,V)
// ---------------------------------------------------------------------------
__global__ void __launch_bounds__(256)
gemm_tn(const __nv_bfloat16* __restrict__ A,
        const __nv_bfloat16* __restrict__ B0, const __nv_bfloat16* __restrict__ B1,
        const float* __restrict__ bias0, const float* __restrict__ bias1,
        __nv_bfloat16* __restrict__ C0, __nv_bfloat16* __restrict__ C1,
        int M, int N, int K)
{
    const __nv_bfloat16* Bm = blockIdx.z ? B1 : B0;
    const float* bias       = blockIdx.z ? bias1 : bias0;
    __nv_bfloat16* C        = blockIdx.z ? C1 : C0;

    __shared__ __align__(128) __nv_bfloat16 As[2][128][32 + APAD];
    __shared__ __align__(128) __nv_bfloat16 Bs[2][32][128 + BPAD];
    __shared__ float bsm[128];

    const int tid = threadIdx.x, wid = tid >> 5, lane = tid & 31;
    const int warpM = wid & 3, warpN = wid >> 2;
    const int m0 = blockIdx.y * 128, n0 = blockIdx.x * 128;
    const int NC = K >> 5;

    if (bias && tid < 128) bsm[tid] = bias[n0 + tid];

    float d[2][8][4];
    #pragma unroll
    for (int i = 0; i < 2; i++)
        #pragma unroll
        for (int j = 0; j < 8; j++)
            #pragma unroll
            for (int q = 0; q < 4; q++) d[i][j][q] = 0.0f;

    auto load_chunk = [&](int c) {
        int buf = c & 1;
        #pragma unroll
        for (int h = 0; h < 2; h++) {
            int p = h * 256 + tid;
            {
                int row = p >> 2, pc = p & 3;
                cp_async16(smem_u32(&As[buf][row][pc * 8]),
                           A + (size_t)(m0 + row) * K + c * 32 + pc * 8);
            }
            {
                int row = p >> 4, pc = p & 15;
                cp_async16(smem_u32(&Bs[buf][row][pc * 8]),
                           Bm + (size_t)(c * 32 + row) * N + n0 + pc * 8);
            }
        }
        CP_COMMIT();
    };

    load_chunk(0);

    for (int c = 0; c < NC; c++) {
        int buf = c & 1;
        if (c + 1 < NC) { load_chunk(c + 1); CP_WAIT(1); }
        else            { CP_WAIT(0); }
        __syncthreads();

        #pragma unroll
        for (int ks = 0; ks < 2; ks++) {
            uint32_t a[2][4];
            #pragma unroll
            for (int fm = 0; fm < 2; fm++) {
                int r  = warpM * 32 + fm * 16 + (lane & 7) + ((lane >> 3) & 1) * 8;
                int kk = ks * 16 + (lane >> 4) * 8;
                ldmatrix_x4(a[fm], smem_u32(&As[buf][r][kk]));
            }
            uint32_t b[8][2];
            #pragma unroll
            for (int i = 0; i < 4; i++) {
                int kk = ks * 16 + (lane & 15);
                int nn = warpN * 64 + i * 16 + (lane >> 4) * 8;
                uint32_t tmp[4];
                ldmatrix_x4_trans(tmp, smem_u32(&Bs[buf][kk][nn]));
                b[2*i][0]   = tmp[0]; b[2*i][1]   = tmp[1];
                b[2*i+1][0] = tmp[2]; b[2*i+1][1] = tmp[3];
            }
            #pragma unroll
            for (int fm = 0; fm < 2; fm++)
                #pragma unroll
                for (int fn = 0; fn < 8; fn++)
                    mma16816(d[fm][fn], a[fm], b[fn]);
        }
        __syncthreads();
    }

    const int mb = m0 + warpM * 32, nb = warpN * 64;
    #pragma unroll
    for (int fm = 0; fm < 2; fm++) {
        #pragma unroll
        for (int fn = 0; fn < 8; fn++) {
            int r0  = mb + fm * 16 + (lane >> 2);
            int col = nb + fn * 8 + 2 * (lane & 3);
            float bz0 = 0.f, bz1 = 0.f;
            if (bias) { bz0 = bsm[col]; bz1 = bsm[col + 1]; }
            __nv_bfloat162* p0 = (__nv_bfloat162*)(C + (size_t)r0 * N + n0 + col);
            __nv_bfloat162* p1 = (__nv_bfloat162*)(C + (size_t)(r0 + 8) * N + n0 + col);
            *p0 = __floats2bfloat162_rn(d[fm][fn][0] + bz0, d[fm][fn][1] + bz1);
            *p1 = __floats2bfloat162_rn(d[fm][fn][2] + bz0, d[fm][fn][3] + bz1);
        }
    }
}

// ---------------------------------------------------------------------------
// 5) Logits + local softmax stats per (b,t)
// ---------------------------------------------------------------------------
__global__ void logits_kernel(const float* __restrict__ x) {
    int bt = blockIdx.x;
    int b  = bt / T_;
    int tid = threadIdx.x, warp = tid >> 5, lane = tid & 31;

    __shared__ float xs[DIM_];
    __shared__ float ls[S_];
    __shared__ float sm2[2];
    const float4* xr = (const float4*)(x + (size_t)bt * DIM_);
    for (int i = tid; i < DIM_ / 4; i += 256) {
        float4 v = xr[i];
        xs[4*i] = v.x; xs[4*i+1] = v.y; xs[4*i+2] = v.z; xs[4*i+3] = v.w;
    }
    __syncthreads();

    for (int j = warp; j < S_; j += 8) {
        int vs = g_sel[bt * S_ + j];
        const uint4* kr = (const uint4*)(g_Kb + ((size_t)b * V_ + vs) * DIM_);
        float acc = 0.0f;
        #pragma unroll
        for (int i = lane; i < DIM_ / 8; i += 32) {
            uint4 raw = kr[i];
            const __nv_bfloat162* p = (const __nv_bfloat162*)&raw;
            int e = i * 8;
            float2 f0 = __bfloat1622float2(p[0]);
            float2 f1 = __bfloat1622float2(p[1]);
            float2 f2 = __bfloat1622float2(p[2]);
            float2 f3 = __bfloat1622float2(p[3]);
            acc = fmaf(f0.x, xs[e],   acc); acc = fmaf(f0.y, xs[e+1], acc);
            acc = fmaf(f1.x, xs[e+2], acc); acc = fmaf(f1.y, xs[e+3], acc);
            acc = fmaf(f2.x, xs[e+4], acc); acc = fmaf(f2.y, xs[e+5], acc);
            acc = fmaf(f3.x, xs[e+6], acc); acc = fmaf(f3.y, xs[e+7], acc);
        }
        #pragma unroll
        for (int off = 16; off > 0; off >>= 1)
            acc += __shfl_down_sync(0xffffffffu, acc, off);
        if (lane == 0) {
            float lg = acc * (1.0f / 32.0f) - 100.0f;
            g_logit[bt * S_ + j] = lg;
            ls[j] = lg;
        }
    }
    __syncthreads();

    // local max over 64 logits (2 warps)
    if (tid < S_) {
        float m = ls[tid];
        #pragma unroll
        for (int off = 16; off > 0; off >>= 1)
            m = fmaxf(m, __shfl_xor_sync(0xffffffffu, m, off));
        if (lane == 0) sm2[warp] = m;
    }
    __syncthreads();
    float M = fmaxf(sm2[0], sm2[1]);
    if (tid < S_) {
        float e = __expf(ls[tid] - M);
        #pragma unroll
        for (int off = 16; off > 0; off >>= 1)
            e += __shfl_xor_sync(0xffffffffu, e, off);
        if (lane == 0) sm2[warp] = e;
    }
    __syncthreads();
    if (tid == 0) g_ms[bt] = make_float2(M, sm2[0] + sm2[1]);
}

// ---------------------------------------------------------------------------
// 6) Combine per-(b,t) stats -> per-batch (max, sumexp)
// ---------------------------------------------------------------------------
__global__ void softmax_combine_kernel() {
    int b = blockIdx.x, tid = threadIdx.x;   // 256 threads = T_
    __shared__ float shm[256], shs[256];
    float2 v = g_ms[b * T_ + tid];
    shm[tid] = v.x; shs[tid] = v.y;
    __syncthreads();
    for (int s = 128; s > 0; s >>= 1) {
        if (tid < s) shm[tid] = fmaxf(shm[tid], shm[tid + s]);
        __syncthreads();
    }
    float M = shm[0];
    float contrib = v.y * __expf(v.x - M);
    shs[tid] = contrib;
    __syncthreads();
    for (int s = 128; s > 0; s >>= 1) {
        if (tid < s) shs[tid] += shs[tid + s];
        __syncthreads();
    }
    if (tid == 0) { g_red[b * 2] = M; g_red[b * 2 + 1] = shs[0]; }
}

// ---------------------------------------------------------------------------
// 7) Output: out = x + sum_j w_j * V_bf16[sel_j]
// ---------------------------------------------------------------------------
__global__ void attn_out_kernel(const float* __restrict__ x, float* __restrict__ out) {
    int bt = blockIdx.x, b = bt / T_, tid = threadIdx.x;
    __shared__ float w[S_];
    __shared__ int   si[S_];
    if (tid < S_) {
        si[tid] = g_sel[bt * S_ + tid];
        w[tid] = __expf(g_logit[bt * S_ + tid] - g_red[b*2]) / g_red[b*2+1];
    }
    __syncthreads();

    float acc[8] = {0,0,0,0,0,0,0,0};
    const __nv_bfloat16* vb = g_Vb + (size_t)b * V_ * DIM_;
    #pragma unroll 4
    for (int j = 0; j < S_; j++) {
        const uint4* rowp = (const uint4*)(vb + (size_t)si[j] * DIM_);
        uint4 raw = rowp[tid];
        const __nv_bfloat162* p = (const __nv_bfloat162*)&raw;
        float wj = w[j];
        #pragma unroll
        for (int q = 0; q < 4; q++) {
            float2 f = __bfloat1622float2(p[q]);
            acc[2*q]   = fmaf(wj, f.x, acc[2*q]);
            acc[2*q+1] = fmaf(wj, f.y, acc[2*q+1]);
        }
    }
    int c = tid * 8;
    const float4* xr = (const float4*)(x + (size_t)bt * DIM_ + c);
    float4 x0 = xr[0], x1 = xr[1];
    float4 o0 = make_float4(acc[0]+x0.x, acc[1]+x0.y, acc[2]+x0.z, acc[3]+x0.w);
    float4 o1 = make_float4(acc[4]+x1.x, acc[5]+x1.y, acc[6]+x1.z, acc[7]+x1.w);
    float4* op = (float4*)(out + (size_t)bt * DIM_ + c);
    op[0] = o0; op[1] = o1;
}

// ---------------------------------------------------------------------------
// Launch
// ---------------------------------------------------------------------------
extern "C" void kernel_launch(void* const* d_in, const int* in_sizes, int n_in,
                              void* d_out, int out_size)
{
    const float* x      = (const float*)d_in[0];
    const float* vision = (const float*)d_in[1];
    const int*   mask   = (const int*)  d_in[2];
    const float* Wu     = (const float*)d_in[3];
    const float* bu     = (const float*)d_in[4];
    const float* Wk     = (const float*)d_in[5];
    const float* Wv     = (const float*)d_in[6];
    float* out = (float*)d_out;

    void *pvb, *pwu, *pwk, *pwv, *puk, *puv, *pbk, *pbv, *pk, *pv;
    cudaGetSymbolAddress(&pvb, g_visb);
    cudaGetSymbolAddress(&pwu, g_Wub);
    cudaGetSymbolAddress(&pwk, g_Wkb);
    cudaGetSymbolAddress(&pwv, g_Wvb);
    cudaGetSymbolAddress(&puk, g_Wuk);
    cudaGetSymbolAddress(&puv, g_Wuv);
    cudaGetSymbolAddress(&pbk, g_buk);
    cudaGetSymbolAddress(&pbv, g_buv);
    cudaGetSymbolAddress(&pk,  g_Kb);
    cudaGetSymbolAddress(&pv,  g_Vb);

    select_kernel<<<(B_ * T_ + 7) / 8, 256>>>(mask);

    const int n_vis = B_*V_*CV_/4, n_wu = CV_*DIM_/4, n_w = DIM_*DIM_/4;
    convert4_bf16<<<dim3((n_w + 255)/256, 4), 256>>>(
        (const float4*)vision, (__nv_bfloat162*)pvb, n_vis,
        (const float4*)Wu,     (__nv_bfloat162*)pwu, n_wu,
        (const float4*)Wk,     (__nv_bfloat162*)pwk, n_w,
        (const float4*)Wv,     (__nv_bfloat162*)pwv, n_w);

    bias_fold_kernel<<<dim3(DIM_/64, 2), 256>>>(bu, Wk, Wv);

    // Wuk/Wuv split-K: grid (8, 2, 16) = 256 CTAs
    gemm_splitk<<<dim3(DIM_/128, CV_/128, 2*SPLITS), 256>>>(
        (const __nv_bfloat16*)pwu,
        (const __nv_bfloat16*)pwk, (const __nv_bfloat16*)pwv);
    reduce_splitk<<<dim3(CV_*DIM_/4/256, 2), 256>>>();

    // K,V = vision@Wuk/uv + bias (M=4096, N=1024, K=256)
    gemm_tn<<<dim3(DIM_/128, (B_*V_)/128, 2), 256>>>(
        (const __nv_bfloat16*)pvb,
        (const __nv_bfloat16*)puk, (const __nv_bfloat16*)puv,
        (const float*)pbk, (const float*)pbv,
        (__nv_bfloat16*)pk, (__nv_bfloat16*)pv,
        B_*V_, DIM_, CV_);

    logits_kernel<<<B_ * T_, 256>>>(x);
    softmax_combine_kernel<<<B_, 256>>>();
    attn_out_kernel<<<B_ * T_, 128>>>(x, out);
}

// round 7
// speedup vs baseline: 6.6644x; 1.1298x over previous
#include <cuda_runtime.h>
#include <cuda_bf16.h>
#include <cstdint>
#include <math.h>

#define B_   4
#define T_   256
#define V_   1024
#define S_   64
#define DIM_ 1024
#define CV_  256
#define SPLITS 4
#define SK_  (DIM_ / SPLITS)     // 256 K per split

// ---------------------------------------------------------------------------
// Scratch (static device globals)
// ---------------------------------------------------------------------------
__device__ __nv_bfloat16 g_visb[B_ * V_ * CV_];
__device__ __nv_bfloat16 g_Wub [CV_ * DIM_];
__device__ __nv_bfloat16 g_Wkb [DIM_ * DIM_];
__device__ __nv_bfloat16 g_Wvb [DIM_ * DIM_];
__device__ __nv_bfloat16 g_Wuk [CV_ * DIM_];
__device__ __nv_bfloat16 g_Wuv [CV_ * DIM_];
__device__ float         g_part[2 * SPLITS][CV_ * DIM_];  // 8MB
__device__ float         g_buk [DIM_];
__device__ float         g_buv [DIM_];
__device__ __nv_bfloat16 g_Kb  [B_ * V_ * DIM_];
__device__ __nv_bfloat16 g_Vb  [B_ * V_ * DIM_];
__device__ int    g_sel  [B_ * T_ * S_];
__device__ float  g_logit[B_ * T_ * S_];
__device__ float2 g_ms   [B_ * T_];               // per-(b,t) (max, sumexp)

// ---------------------------------------------------------------------------
// helpers
// ---------------------------------------------------------------------------
__device__ __forceinline__ uint32_t smem_u32(const void* p) {
    uint32_t a;
    asm("{ .reg .u64 t; cvta.to.shared.u64 t, %1; cvt.u32.u64 %0, t; }"
        : "=r"(a) : "l"(p));
    return a;
}
__device__ __forceinline__ void cp_async16(uint32_t dst, const void* src) {
    asm volatile("cp.async.cg.shared.global [%0], [%1], 16;" :: "r"(dst), "l"(src));
}
#define CP_COMMIT() asm volatile("cp.async.commit_group;" ::: "memory")
#define CP_WAIT(n)  asm volatile("cp.async.wait_group %0;" :: "n"(n) : "memory")

__device__ __forceinline__ void ldmatrix_x4(uint32_t* r, uint32_t addr) {
    asm volatile("ldmatrix.sync.aligned.m8n8.x4.shared.b16 {%0,%1,%2,%3}, [%4];"
                 : "=r"(r[0]), "=r"(r[1]), "=r"(r[2]), "=r"(r[3]) : "r"(addr));
}
__device__ __forceinline__ void ldmatrix_x4_trans(uint32_t* r, uint32_t addr) {
    asm volatile("ldmatrix.sync.aligned.m8n8.x4.trans.shared.b16 {%0,%1,%2,%3}, [%4];"
                 : "=r"(r[0]), "=r"(r[1]), "=r"(r[2]), "=r"(r[3]) : "r"(addr));
}
__device__ __forceinline__ void mma16816(float* d, const uint32_t* a, const uint32_t* b) {
    asm volatile(
        "mma.sync.aligned.m16n8k16.row.col.f32.bf16.bf16.f32 "
        "{%0,%1,%2,%3},{%4,%5,%6,%7},{%8,%9},{%0,%1,%2,%3};"
        : "+f"(d[0]), "+f"(d[1]), "+f"(d[2]), "+f"(d[3])
        : "r"(a[0]), "r"(a[1]), "r"(a[2]), "r"(a[3]), "r"(b[0]), "r"(b[1]));
}

#define APAD 8
#define BPAD 8

// ---------------------------------------------------------------------------
// 1) prep: y=0 select, y=1..4 converts (vision,Wu,Wk,Wv), y=5 bias fold
// ---------------------------------------------------------------------------
__device__ __forceinline__ void conv_seg(const float4* s, __nv_bfloat162* o, int n) {
    int i = blockIdx.x * 256 + threadIdx.x;
    if (i < n) {
        float4 v = s[i];
        o[2 * i]     = __floats2bfloat162_rn(v.x, v.y);
        o[2 * i + 1] = __floats2bfloat162_rn(v.z, v.w);
    }
}

__global__ void prep_kernel(const int* __restrict__ mask,
                            const float* __restrict__ vision,
                            const float* __restrict__ Wu,
                            const float* __restrict__ bu,
                            const float* __restrict__ Wk,
                            const float* __restrict__ Wv) {
    switch (blockIdx.y) {
    case 0: {   // selection: 128 blocks x 8 warps = 1024 (b,t) warps
        int warp = blockIdx.x * 8 + (threadIdx.x >> 5);
        int lane = threadIdx.x & 31;
        if (blockIdx.x >= 128) return;
        int b = warp / T_, t = warp % T_;
        const int* m = mask + (size_t)b * V_ * T_ + t;
        int count = 0;
        #pragma unroll 4
        for (int base = 0; base < V_; base += 32) {
            int v = base + lane;
            int val = m[(size_t)v * T_];
            unsigned bal = __ballot_sync(0xffffffffu, val != 0);
            if (val != 0) {
                int pos = count + __popc(bal & ((1u << lane) - 1u));
                if (pos < S_) g_sel[warp * S_ + pos] = v;
            }
            count += __popc(bal);
        }
        break; }
    case 1: conv_seg((const float4*)vision, (__nv_bfloat162*)g_visb, B_*V_*CV_/4); break;
    case 2: conv_seg((const float4*)Wu,     (__nv_bfloat162*)g_Wub,  CV_*DIM_/4);  break;
    case 3: conv_seg((const float4*)Wk,     (__nv_bfloat162*)g_Wkb,  DIM_*DIM_/4); break;
    case 4: conv_seg((const float4*)Wv,     (__nv_bfloat162*)g_Wvb,  DIM_*DIM_/4); break;
    default: {  // bias fold: 32 blocks; kv = x&1, nblk = x>>1
        if (blockIdx.x >= 32) return;
        int kv = blockIdx.x & 1;
        const float* W = kv ? Wv : Wk;
        float* outp    = kv ? g_buv : g_buk;
        int tx = threadIdx.x & 63, ty = threadIdx.x >> 6;
        int n = (blockIdx.x >> 1) * 64 + tx;
        __shared__ float partial[4][64];
        float acc = 0.0f;
        int c0 = ty * 256;
        #pragma unroll 8
        for (int c = c0; c < c0 + 256; c++)
            acc = fmaf(bu[c], W[(size_t)c * DIM_ + n], acc);
        partial[ty][tx] = acc;
        __syncthreads();
        if (ty == 0)
            outp[n] = partial[0][tx] + partial[1][tx] + partial[2][tx] + partial[3][tx];
        break; }
    }
}

// ---------------------------------------------------------------------------
// 2a) Split-K GEMM for Wuk/Wuv (fp32 partials). grid (8, 2, 2*SPLITS)
// ---------------------------------------------------------------------------
__global__ void __launch_bounds__(256)
gemm_splitk(const __nv_bfloat16* __restrict__ A,
            const __nv_bfloat16* __restrict__ B0, const __nv_bfloat16* __restrict__ B1)
{
    const int kv = blockIdx.z & 1, split = blockIdx.z >> 1;
    const __nv_bfloat16* Bm = kv ? B1 : B0;
    float* Cp = g_part[kv * SPLITS + split];
    const int N = DIM_, K = DIM_;
    const int kbase = split * SK_;

    __shared__ __align__(128) __nv_bfloat16 As[2][128][32 + APAD];
    __shared__ __align__(128) __nv_bfloat16 Bs[2][32][128 + BPAD];

    const int tid = threadIdx.x, wid = tid >> 5, lane = tid & 31;
    const int warpM = wid & 3, warpN = wid >> 2;
    const int m0 = blockIdx.y * 128, n0 = blockIdx.x * 128;
    const int NC = SK_ >> 5;                       // 8 chunks

    float d[2][8][4];
    #pragma unroll
    for (int i = 0; i < 2; i++)
        #pragma unroll
        for (int j = 0; j < 8; j++)
            #pragma unroll
            for (int q = 0; q < 4; q++) d[i][j][q] = 0.0f;

    auto load_chunk = [&](int c) {
        int buf = c & 1;
        #pragma unroll
        for (int h = 0; h < 2; h++) {
            int p = h * 256 + tid;
            {
                int row = p >> 2, pc = p & 3;
                cp_async16(smem_u32(&As[buf][row][pc * 8]),
                           A + (size_t)(m0 + row) * K + kbase + c * 32 + pc * 8);
            }
            {
                int row = p >> 4, pc = p & 15;
                cp_async16(smem_u32(&Bs[buf][row][pc * 8]),
                           Bm + (size_t)(kbase + c * 32 + row) * N + n0 + pc * 8);
            }
        }
        CP_COMMIT();
    };

    load_chunk(0);

    for (int c = 0; c < NC; c++) {
        int buf = c & 1;
        if (c + 1 < NC) { load_chunk(c + 1); CP_WAIT(1); }
        else            { CP_WAIT(0); }
        __syncthreads();

        #pragma unroll
        for (int ks = 0; ks < 2; ks++) {
            uint32_t a[2][4];
            #pragma unroll
            for (int fm = 0; fm < 2; fm++) {
                int r  = warpM * 32 + fm * 16 + (lane & 7) + ((lane >> 3) & 1) * 8;
                int kk = ks * 16 + (lane >> 4) * 8;
                ldmatrix_x4(a[fm], smem_u32(&As[buf][r][kk]));
            }
            uint32_t b[8][2];
            #pragma unroll
            for (int i = 0; i < 4; i++) {
                int kk = ks * 16 + (lane & 15);
                int nn = warpN * 64 + i * 16 + (lane >> 4) * 8;
                uint32_t tmp[4];
                ldmatrix_x4_trans(tmp, smem_u32(&Bs[buf][kk][nn]));
                b[2*i][0]   = tmp[0]; b[2*i][1]   = tmp[1];
                b[2*i+1][0] = tmp[2]; b[2*i+1][1] = tmp[3];
            }
            #pragma unroll
            for (int fm = 0; fm < 2; fm++)
                #pragma unroll
                for (int fn = 0; fn < 8; fn++)
                    mma16816(d[fm][fn], a[fm], b[fn]);
        }
        __syncthreads();
    }

    const int mb = m0 + warpM * 32, nb = warpN * 64;
    #pragma unroll
    for (int fm = 0; fm < 2; fm++) {
        #pragma unroll
        for (int fn = 0; fn < 8; fn++) {
            int r0  = mb + fm * 16 + (lane >> 2);
            int col = n0 + nb + fn * 8 + 2 * (lane & 3);
            *(float2*)(Cp + (size_t)r0 * N + col)       = make_float2(d[fm][fn][0], d[fm][fn][1]);
            *(float2*)(Cp + (size_t)(r0 + 8) * N + col) = make_float2(d[fm][fn][2], d[fm][fn][3]);
        }
    }
}

// 2b) Reduce split-K partials -> bf16 Wuk / Wuv
__global__ void reduce_splitk() {
    int i  = blockIdx.x * blockDim.x + threadIdx.x;
    int kv = blockIdx.y;
    float4 acc = make_float4(0.f, 0.f, 0.f, 0.f);
    #pragma unroll
    for (int s = 0; s < SPLITS; s++) {
        float4 p = ((const float4*)g_part[kv * SPLITS + s])[i];
        acc.x += p.x; acc.y += p.y; acc.z += p.z; acc.w += p.w;
    }
    __nv_bfloat162* o = (__nv_bfloat162*)(kv ? g_Wuv : g_Wuk);
    o[2 * i]     = __floats2bfloat162_rn(acc.x, acc.y);
    o[2 * i + 1] = __floats2bfloat162_rn(acc.z, acc.w);
}

// ---------------------------------------------------------------------------
// 2c) KV GEMM: BK=64, dynamic smem 2-stage. z: (Wuk,buk,K)/(Wuv,buv,V)
// ---------------------------------------------------------------------------
#define TNS_A_ELEMS (128 * 72)
#define TNS_B_ELEMS (64 * 136)
#define TNS_STAGE   ((TNS_A_ELEMS + TNS_B_ELEMS) * 2)   // 35840 bytes
#define TNS_SMEM    (2 * TNS_STAGE)                      // 71680

__global__ void __launch_bounds__(256)
gemm_tn(const __nv_bfloat16* __restrict__ A,
        const __nv_bfloat16* __restrict__ B0, const __nv_bfloat16* __restrict__ B1,
        const float* __restrict__ bias0, const float* __restrict__ bias1,
        __nv_bfloat16* __restrict__ C0, __nv_bfloat16* __restrict__ C1,
        int M, int N, int K)
{
    const __nv_bfloat16* Bm = blockIdx.z ? B1 : B0;
    const float* bias       = blockIdx.z ? bias1 : bias0;
    __nv_bfloat16* C        = blockIdx.z ? C1 : C0;

    extern __shared__ char dsm[];
    __shared__ float bsm[128];

    const int tid = threadIdx.x, wid = tid >> 5, lane = tid & 31;
    const int warpM = wid & 3, warpN = wid >> 2;
    const int m0 = blockIdx.y * 128, n0 = blockIdx.x * 128;
    const int NC = K >> 6;                         // BK=64

    if (bias && tid < 128) bsm[tid] = bias[n0 + tid];

    auto Aadr = [&](int s, int r, int c) {
        return (__nv_bfloat16*)(dsm + s * TNS_STAGE) + r * 72 + c;
    };
    auto Badr = [&](int s, int r, int c) {
        return (__nv_bfloat16*)(dsm + s * TNS_STAGE + TNS_A_ELEMS * 2) + r * 136 + c;
    };

    float d[2][8][4];
    #pragma unroll
    for (int i = 0; i < 2; i++)
        #pragma unroll
        for (int j = 0; j < 8; j++)
            #pragma unroll
            for (int q = 0; q < 4; q++) d[i][j][q] = 0.0f;

    // per chunk: A 128x64 = 1024 pieces, B 64x128 = 1024 pieces
    auto load_chunk = [&](int c) {
        int buf = c & 1;
        #pragma unroll
        for (int h = 0; h < 4; h++) {
            int p = h * 256 + tid;
            {
                int row = p >> 3, pc = p & 7;
                cp_async16(smem_u32(Aadr(buf, row, pc * 8)),
                           A + (size_t)(m0 + row) * K + c * 64 + pc * 8);
            }
            {
                int row = p >> 4, pc = p & 15;
                cp_async16(smem_u32(Badr(buf, row, pc * 8)),
                           Bm + (size_t)(c * 64 + row) * N + n0 + pc * 8);
            }
        }
        CP_COMMIT();
    };

    load_chunk(0);

    for (int c = 0; c < NC; c++) {
        int buf = c & 1;
        if (c + 1 < NC) { load_chunk(c + 1); CP_WAIT(1); }
        else            { CP_WAIT(0); }
        __syncthreads();

        #pragma unroll
        for (int ks = 0; ks < 4; ks++) {
            uint32_t a[2][4];
            #pragma unroll
            for (int fm = 0; fm < 2; fm++) {
                int r  = warpM * 32 + fm * 16 + (lane & 7) + ((lane >> 3) & 1) * 8;
                int kk = ks * 16 + (lane >> 4) * 8;
                ldmatrix_x4(a[fm], smem_u32(Aadr(buf, r, kk)));
            }
            uint32_t b[8][2];
            #pragma unroll
            for (int i = 0; i < 4; i++) {
                int kk = ks * 16 + (lane & 15);
                int nn = warpN * 64 + i * 16 + (lane >> 4) * 8;
                uint32_t tmp[4];
                ldmatrix_x4_trans(tmp, smem_u32(Badr(buf, kk, nn)));
                b[2*i][0]   = tmp[0]; b[2*i][1]   = tmp[1];
                b[2*i+1][0] = tmp[2]; b[2*i+1][1] = tmp[3];
            }
            #pragma unroll
            for (int fm = 0; fm < 2; fm++)
                #pragma unroll
                for (int fn = 0; fn < 8; fn++)
                    mma16816(d[fm][fn], a[fm], b[fn]);
        }
        __syncthreads();
    }

    const int mb = m0 + warpM * 32, nb = warpN * 64;
    #pragma unroll
    for (int fm = 0; fm < 2; fm++) {
        #pragma unroll
        for (int fn = 0; fn < 8; fn++) {
            int r0  = mb + fm * 16 + (lane >> 2);
            int col = nb + fn * 8 + 2 * (lane & 3);
            float bz0 = 0.f, bz1 = 0.f;
            if (bias) { bz0 = bsm[col]; bz1 = bsm[col + 1]; }
            __nv_bfloat162* p0 = (__nv_bfloat162*)(C + (size_t)r0 * N + n0 + col);
            __nv_bfloat162* p1 = (__nv_bfloat162*)(C + (size_t)(r0 + 8) * N + n0 + col);
            *p0 = __floats2bfloat162_rn(d[fm][fn][0] + bz0, d[fm][fn][1] + bz1);
            *p1 = __floats2bfloat162_rn(d[fm][fn][2] + bz0, d[fm][fn][3] + bz1);
        }
    }
}

// ---------------------------------------------------------------------------
// 3) Logits + local softmax stats per (b,t)
// ---------------------------------------------------------------------------
__global__ void logits_kernel(const float* __restrict__ x) {
    int bt = blockIdx.x;
    int b  = bt / T_;
    int tid = threadIdx.x, warp = tid >> 5, lane = tid & 31;

    __shared__ float xs[DIM_];
    __shared__ float ls[S_];
    __shared__ float sm2[2];
    const float4* xr = (const float4*)(x + (size_t)bt * DIM_);
    for (int i = tid; i < DIM_ / 4; i += 256) {
        float4 v = xr[i];
        xs[4*i] = v.x; xs[4*i+1] = v.y; xs[4*i+2] = v.z; xs[4*i+3] = v.w;
    }
    __syncthreads();

    for (int j = warp; j < S_; j += 8) {
        int vs = g_sel[bt * S_ + j];
        const uint4* kr = (const uint4*)(g_Kb + ((size_t)b * V_ + vs) * DIM_);
        float acc = 0.0f;
        #pragma unroll
        for (int i = lane; i < DIM_ / 8; i += 32) {
            uint4 raw = kr[i];
            const __nv_bfloat162* p = (const __nv_bfloat162*)&raw;
            int e = i * 8;
            float2 f0 = __bfloat1622float2(p[0]);
            float2 f1 = __bfloat1622float2(p[1]);
            float2 f2 = __bfloat1622float2(p[2]);
            float2 f3 = __bfloat1622float2(p[3]);
            acc = fmaf(f0.x, xs[e],   acc); acc = fmaf(f0.y, xs[e+1], acc);
            acc = fmaf(f1.x, xs[e+2], acc); acc = fmaf(f1.y, xs[e+3], acc);
            acc = fmaf(f2.x, xs[e+4], acc); acc = fmaf(f2.y, xs[e+5], acc);
            acc = fmaf(f3.x, xs[e+6], acc); acc = fmaf(f3.y, xs[e+7], acc);
        }
        #pragma unroll
        for (int off = 16; off > 0; off >>= 1)
            acc += __shfl_down_sync(0xffffffffu, acc, off);
        if (lane == 0) {
            float lg = acc * (1.0f / 32.0f) - 100.0f;
            g_logit[bt * S_ + j] = lg;
            ls[j] = lg;
        }
    }
    __syncthreads();

    if (tid < S_) {
        float m = ls[tid];
        #pragma unroll
        for (int off = 16; off > 0; off >>= 1)
            m = fmaxf(m, __shfl_xor_sync(0xffffffffu, m, off));
        if (lane == 0) sm2[warp] = m;
    }
    __syncthreads();
    float M = fmaxf(sm2[0], sm2[1]);
    if (tid < S_) {
        float e = __expf(ls[tid] - M);
        #pragma unroll
        for (int off = 16; off > 0; off >>= 1)
            e += __shfl_xor_sync(0xffffffffu, e, off);
        if (lane == 0) sm2[warp] = e;
    }
    __syncthreads();
    if (tid == 0) g_ms[bt] = make_float2(M, sm2[0] + sm2[1]);
}

// ---------------------------------------------------------------------------
// 4) Output (with fused per-batch softmax combine): 128 threads per (b,t)
// ---------------------------------------------------------------------------
__global__ void attn_out_kernel(const float* __restrict__ x, float* __restrict__ out) {
    int bt = blockIdx.x, b = bt / T_, tid = threadIdx.x;

    // per-batch (M,S) from 256 per-token pairs
    __shared__ float shm[128], shs[128];
    float2 v0 = g_ms[b * T_ + tid];
    float2 v1 = g_ms[b * T_ + 128 + tid];
    shm[tid] = fmaxf(v0.x, v1.x);
    __syncthreads();
    for (int s = 64; s > 0; s >>= 1) {
        if (tid < s) shm[tid] = fmaxf(shm[tid], shm[tid + s]);
        __syncthreads();
    }
    float M = shm[0];
    shs[tid] = v0.y * __expf(v0.x - M) + v1.y * __expf(v1.x - M);
    __syncthreads();
    for (int s = 64; s > 0; s >>= 1) {
        if (tid < s) shs[tid] += shs[tid + s];
        __syncthreads();
    }
    float Sb = shs[0];

    __shared__ float w[S_];
    __shared__ int   si[S_];
    if (tid < S_) {
        si[tid] = g_sel[bt * S_ + tid];
        w[tid] = __expf(g_logit[bt * S_ + tid] - M) / Sb;
    }
    __syncthreads();

    float acc[8] = {0,0,0,0,0,0,0,0};
    const __nv_bfloat16* vb = g_Vb + (size_t)b * V_ * DIM_;
    #pragma unroll 4
    for (int j = 0; j < S_; j++) {
        const uint4* rowp = (const uint4*)(vb + (size_t)si[j] * DIM_);
        uint4 raw = rowp[tid];
        const __nv_bfloat162* p = (const __nv_bfloat162*)&raw;
        float wj = w[j];
        #pragma unroll
        for (int q = 0; q < 4; q++) {
            float2 f = __bfloat1622float2(p[q]);
            acc[2*q]   = fmaf(wj, f.x, acc[2*q]);
            acc[2*q+1] = fmaf(wj, f.y, acc[2*q+1]);
        }
    }
    int c = tid * 8;
    const float4* xr = (const float4*)(x + (size_t)bt * DIM_ + c);
    float4 x0 = xr[0], x1 = xr[1];
    float4 o0 = make_float4(acc[0]+x0.x, acc[1]+x0.y, acc[2]+x0.z, acc[3]+x0.w);
    float4 o1 = make_float4(acc[4]+x1.x, acc[5]+x1.y, acc[6]+x1.z, acc[7]+x1.w);
    float4* op = (float4*)(out + (size_t)bt * DIM_ + c);
    op[0] = o0; op[1] = o1;
}

// ---------------------------------------------------------------------------
// Launch
// ---------------------------------------------------------------------------
extern "C" void kernel_launch(void* const* d_in, const int* in_sizes, int n_in,
                              void* d_out, int out_size)
{
    const float* x      = (const float*)d_in[0];
    const float* vision = (const float*)d_in[1];
    const int*   mask   = (const int*)  d_in[2];
    const float* Wu     = (const float*)d_in[3];
    const float* bu     = (const float*)d_in[4];
    const float* Wk     = (const float*)d_in[5];
    const float* Wv     = (const float*)d_in[6];
    float* out = (float*)d_out;

    void *pvb, *pwu, *pwk, *pwv, *puk, *puv, *pbk, *pbv, *pk, *pv;
    cudaGetSymbolAddress(&pvb, g_visb);
    cudaGetSymbolAddress(&pwu, g_Wub);
    cudaGetSymbolAddress(&pwk, g_Wkb);
    cudaGetSymbolAddress(&pwv, g_Wvb);
    cudaGetSymbolAddress(&puk, g_Wuk);
    cudaGetSymbolAddress(&puv, g_Wuv);
    cudaGetSymbolAddress(&pbk, g_buk);
    cudaGetSymbolAddress(&pbv, g_buv);
    cudaGetSymbolAddress(&pk,  g_Kb);
    cudaGetSymbolAddress(&pv,  g_Vb);

    static int smem_set = 0;
    if (!smem_set) {
        cudaFuncSetAttribute(gemm_tn, cudaFuncAttributeMaxDynamicSharedMemorySize, TNS_SMEM);
        smem_set = 1;
    }

    // 1) prep: select / converts / bias fold
    prep_kernel<<<dim3(1024, 6), 256>>>(mask, vision, Wu, bu, Wk, Wv);

    // 2) Wuk/Wuv split-K + reduce
    gemm_splitk<<<dim3(DIM_/128, CV_/128, 2*SPLITS), 256>>>(
        (const __nv_bfloat16*)pwu,
        (const __nv_bfloat16*)pwk, (const __nv_bfloat16*)pwv);
    reduce_splitk<<<dim3(CV_*DIM_/4/256, 2), 256>>>();

    // 3) K,V = vision@Wuk/uv + bias
    gemm_tn<<<dim3(DIM_/128, (B_*V_)/128, 2), 256, TNS_SMEM>>>(
        (const __nv_bfloat16*)pvb,
        (const __nv_bfloat16*)puk, (const __nv_bfloat16*)puv,
        (const float*)pbk, (const float*)pbv,
        (__nv_bfloat16*)pk, (__nv_bfloat16*)pv,
        B_*V_, DIM_, CV_);

    // 4) tail
    logits_kernel<<<B_ * T_, 256>>>(x);
    attn_out_kernel<<<B_ * T_, 128>>>(x, out);
}